// round 1
// baseline (speedup 1.0000x reference)
#include <cuda_runtime.h>
#include <cuda_bf16.h>
#include <stdint.h>

// Problem constants (fixed by the reference setup)
#define BB 32
#define TT 2000
#define HH 768
#define SS 100
#define NVV 100
#define BSROWS (BB * SS)        // 3200
#define K2 (2 * HH)             // 1536
#define ROWSTRIDE (NVV + TT)    // 2100 rows per batch in vision_trace_feat

// Scratch (device globals; no allocation allowed)
__device__ float g_agg[BSROWS * HH];   // segment means, row-major (3200, 768)
__device__ float g_vis[BB * HH];       // per-batch vision mean
__device__ float g_v2[BB * HH];        // vision_feat @ W2^T + bias

// ---------------------------------------------------------------------------
// Kernel 1: vision_feat[b][h] = mean over first NV rows
// ---------------------------------------------------------------------------
__global__ __launch_bounds__(256) void vis_mean_kernel(const float* __restrict__ feat) {
    int b = blockIdx.x;
    const float* base = feat + (size_t)b * ROWSTRIDE * HH;
    for (int h4 = threadIdx.x; h4 < HH / 4; h4 += blockDim.x) {
        float4 acc = make_float4(0.f, 0.f, 0.f, 0.f);
        #pragma unroll 4
        for (int r = 0; r < NVV; r++) {
            float4 v = *(const float4*)&base[(size_t)r * HH + h4 * 4];
            acc.x += v.x; acc.y += v.y; acc.z += v.z; acc.w += v.w;
        }
        const float inv = 1.0f / (float)NVV;
        acc.x *= inv; acc.y *= inv; acc.z *= inv; acc.w *= inv;
        *(float4*)&g_vis[b * HH + h4 * 4] = acc;
    }
}

// ---------------------------------------------------------------------------
// Kernel 2: segment means. One block per (b, s). General mask handling:
// scan this batch's mask row, collect matching token indices, average rows.
// ---------------------------------------------------------------------------
__global__ __launch_bounds__(256) void agg_kernel(const float* __restrict__ feat,
                                                  const int* __restrict__ mask) {
    int blk = blockIdx.x;            // 0..3199
    int b = blk / SS;
    int s = blk % SS;

    __shared__ int s_list[TT];
    __shared__ int s_cnt;
    if (threadIdx.x == 0) s_cnt = 0;
    __syncthreads();

    const int* mrow = mask + (size_t)b * TT;
    for (int t = threadIdx.x; t < TT; t += blockDim.x) {
        if (mrow[t] == s + 1) {
            int pos = atomicAdd(&s_cnt, 1);
            s_list[pos] = t;
        }
    }
    __syncthreads();

    int cnt = s_cnt;
    float inv = (cnt > 0) ? (1.0f / (float)cnt) : 0.0f;

    const float* base = feat + ((size_t)b * ROWSTRIDE + NVV) * HH;
    for (int h4 = threadIdx.x; h4 < HH / 4; h4 += blockDim.x) {
        float4 acc = make_float4(0.f, 0.f, 0.f, 0.f);
        for (int i = 0; i < cnt; i++) {
            float4 v = *(const float4*)&base[(size_t)s_list[i] * HH + h4 * 4];
            acc.x += v.x; acc.y += v.y; acc.z += v.z; acc.w += v.w;
        }
        acc.x *= inv; acc.y *= inv; acc.z *= inv; acc.w *= inv;
        *(float4*)&g_agg[(size_t)blk * HH + h4 * 4] = acc;
    }
}

// ---------------------------------------------------------------------------
// Kernel 3: g_v2[b][n] = sum_k vision[b][k] * w_merge[n][H + k] + bias[n]
// Tiny (75 MFLOP); one block per batch.
// ---------------------------------------------------------------------------
__global__ __launch_bounds__(256) void v2_kernel(const float* __restrict__ w,
                                                 const float* __restrict__ bias) {
    int b = blockIdx.x;
    __shared__ float sv[HH];
    for (int h = threadIdx.x; h < HH; h += blockDim.x) sv[h] = g_vis[b * HH + h];
    __syncthreads();

    for (int n = threadIdx.x; n < HH; n += blockDim.x) {
        float acc = bias[n];
        const float* wr = w + (size_t)n * K2 + HH;   // W2 row n
        #pragma unroll 4
        for (int k = 0; k < HH; k += 4) {
            float4 wv = *(const float4*)&wr[k];
            acc += sv[k] * wv.x + sv[k + 1] * wv.y + sv[k + 2] * wv.z + sv[k + 3] * wv.w;
        }
        g_v2[b * HH + n] = acc;
    }
}

// ---------------------------------------------------------------------------
// Kernel 4: main GEMM. out[m][n] = sum_k g_agg[m][k] * w_merge[n][k] + g_v2[m/S][n]
// M=3200, N=768, K=768. BM=128, BN=64, BK=16, 256 threads, 8x4 per thread.
// ---------------------------------------------------------------------------
#define GBM 128
#define GBN 64
#define GBK 16

__global__ __launch_bounds__(256) void gemm_kernel(const float* __restrict__ w,
                                                   float* __restrict__ out) {
    __shared__ float As[GBK][GBM + 4];   // transposed A tile, padded
    __shared__ float Bs[GBK][GBN + 4];   // transposed W1 tile, padded

    const int tx = threadIdx.x;          // 0..15 -> n
    const int ty = threadIdx.y;          // 0..15 -> m
    const int tid = ty * 16 + tx;
    const int n0 = blockIdx.x * GBN;
    const int m0 = blockIdx.y * GBM;

    float acc[8][4];
    #pragma unroll
    for (int i = 0; i < 8; i++)
        #pragma unroll
        for (int j = 0; j < 4; j++) acc[i][j] = 0.0f;

    const int lr = tid >> 2;             // 0..63
    const int lc = (tid & 3) * 4;        // 0,4,8,12

    for (int k0 = 0; k0 < HH; k0 += GBK) {
        float4 a0 = *(const float4*)&g_agg[(size_t)(m0 + lr) * HH + k0 + lc];
        float4 a1 = *(const float4*)&g_agg[(size_t)(m0 + lr + 64) * HH + k0 + lc];
        float4 bv = *(const float4*)&w[(size_t)(n0 + lr) * K2 + k0 + lc];
        __syncthreads();
        As[lc + 0][lr] = a0.x; As[lc + 1][lr] = a0.y;
        As[lc + 2][lr] = a0.z; As[lc + 3][lr] = a0.w;
        As[lc + 0][lr + 64] = a1.x; As[lc + 1][lr + 64] = a1.y;
        As[lc + 2][lr + 64] = a1.z; As[lc + 3][lr + 64] = a1.w;
        Bs[lc + 0][lr] = bv.x; Bs[lc + 1][lr] = bv.y;
        Bs[lc + 2][lr] = bv.z; Bs[lc + 3][lr] = bv.w;
        __syncthreads();

        #pragma unroll
        for (int k = 0; k < GBK; k++) {
            float4 t0 = *(const float4*)&As[k][ty * 8];
            float4 t1 = *(const float4*)&As[k][ty * 8 + 4];
            float4 tb = *(const float4*)&Bs[k][tx * 4];
            float af[8] = {t0.x, t0.y, t0.z, t0.w, t1.x, t1.y, t1.z, t1.w};
            float bf[4] = {tb.x, tb.y, tb.z, tb.w};
            #pragma unroll
            for (int i = 0; i < 8; i++)
                #pragma unroll
                for (int j = 0; j < 4; j++)
                    acc[i][j] += af[i] * bf[j];
        }
    }

    // Epilogue: add broadcast vision term + write float4
    #pragma unroll
    for (int i = 0; i < 8; i++) {
        int m = m0 + ty * 8 + i;
        int b = m / SS;
        float4 v2 = *(const float4*)&g_v2[b * HH + n0 + tx * 4];
        float4 o;
        o.x = acc[i][0] + v2.x;
        o.y = acc[i][1] + v2.y;
        o.z = acc[i][2] + v2.z;
        o.w = acc[i][3] + v2.w;
        *(float4*)&out[(size_t)m * HH + n0 + tx * 4] = o;
    }
}

// ---------------------------------------------------------------------------
extern "C" void kernel_launch(void* const* d_in, const int* in_sizes, int n_in,
                              void* d_out, int out_size) {
    const float* feat = (const float*)d_in[0];       // (B, NV+T, H) f32
    const int*   mask = (const int*)d_in[1];         // (B, T) i32
    const float* w    = (const float*)d_in[2];       // (H, 2H) f32
    const float* bias = (const float*)d_in[3];       // (H,) f32
    float* out = (float*)d_out;                      // (B, S, H) f32

    vis_mean_kernel<<<BB, 256>>>(feat);
    agg_kernel<<<BSROWS, 256>>>(feat, mask);
    v2_kernel<<<BB, 256>>>(w, bias);
    dim3 ggrid(HH / GBN, BSROWS / GBM);              // (12, 25)
    dim3 gblk(16, 16);
    gemm_kernel<<<ggrid, gblk>>>(w, out);
}

// round 5
// speedup vs baseline: 1.8289x; 1.8289x over previous
#include <cuda_runtime.h>
#include <cuda_bf16.h>
#include <stdint.h>

// Problem constants
#define BB 32
#define TT 2000
#define HH 768
#define SS 100
#define NVV 100
#define BSROWS 3200            // B*S
#define ROWSTRIDE 2100         // NV + T
#define K2 1536                // 2*H

// ---------------------------------------------------------------------------
// Scratch (device globals; allocation forbidden)
// ---------------------------------------------------------------------------
__device__ unsigned short g_ahi[BSROWS * HH];   // bf16 hi of segment means
__device__ unsigned short g_alo[BSROWS * HH];   // bf16 lo
__device__ unsigned short g_w1h[HH * HH];       // bf16 hi of W1 (w[:, :768])
__device__ unsigned short g_w1l[HH * HH];
__device__ float g_vispart[BB * 4 * HH];        // partial sums of vision rows
__device__ float g_v2[BB * HH];                 // vision @ W2^T + bias

// ---------------------------------------------------------------------------
// Helpers
// ---------------------------------------------------------------------------
__device__ __forceinline__ uint32_t smem_u32(const void* p) {
    uint32_t a;
    asm("{ .reg .u64 t; cvta.to.shared.u64 t, %1; cvt.u32.u64 %0, t; }" : "=r"(a) : "l"(p));
    return a;
}
__device__ __forceinline__ void cpasync16(uint32_t saddr, const void* g) {
    asm volatile("cp.async.cg.shared.global [%0], [%1], 16;" :: "r"(saddr), "l"(g));
}
#define CP_COMMIT() asm volatile("cp.async.commit_group;" ::: "memory")

__device__ __forceinline__ void ldsm_x4(uint32_t* r, uint32_t addr) {
    asm volatile("ldmatrix.sync.aligned.m8n8.x4.shared.b16 {%0,%1,%2,%3}, [%4];"
                 : "=r"(r[0]), "=r"(r[1]), "=r"(r[2]), "=r"(r[3]) : "r"(addr));
}
__device__ __forceinline__ void ldsm_x2(uint32_t* r, uint32_t addr) {
    asm volatile("ldmatrix.sync.aligned.m8n8.x2.shared.b16 {%0,%1}, [%2];"
                 : "=r"(r[0]), "=r"(r[1]) : "r"(addr));
}
__device__ __forceinline__ void mma_bf16(float* c, const uint32_t* a, const uint32_t* b) {
    asm volatile("mma.sync.aligned.m16n8k16.row.col.f32.bf16.bf16.f32 "
                 "{%0,%1,%2,%3}, {%4,%5,%6,%7}, {%8,%9}, {%0,%1,%2,%3};"
                 : "+f"(c[0]), "+f"(c[1]), "+f"(c[2]), "+f"(c[3])
                 : "r"(a[0]), "r"(a[1]), "r"(a[2]), "r"(a[3]), "r"(b[0]), "r"(b[1]));
}

// bf16 hi/lo split
__device__ __forceinline__ void split1(float x, unsigned short& h, unsigned short& l) {
    __nv_bfloat16 bh = __float2bfloat16_rn(x);
    h = __bfloat16_as_ushort(bh);
    l = __bfloat16_as_ushort(__float2bfloat16_rn(x - __bfloat162float(bh)));
}

// ---------------------------------------------------------------------------
// Kernel: vision partial sums. grid (32, 4), 192 threads. Each block sums 25 rows.
// ---------------------------------------------------------------------------
__global__ __launch_bounds__(192) void vis_part_kernel(const float* __restrict__ feat) {
    int b = blockIdx.x, part = blockIdx.y;
    const float* base = feat + ((size_t)b * ROWSTRIDE + part * 25) * HH;
    int h4 = threadIdx.x;                      // 0..191
    float4 acc = make_float4(0.f, 0.f, 0.f, 0.f);
    int r = 0;
    for (; r + 4 <= 25; r += 4) {
        float4 v0 = *(const float4*)&base[(size_t)(r + 0) * HH + h4 * 4];
        float4 v1 = *(const float4*)&base[(size_t)(r + 1) * HH + h4 * 4];
        float4 v2 = *(const float4*)&base[(size_t)(r + 2) * HH + h4 * 4];
        float4 v3 = *(const float4*)&base[(size_t)(r + 3) * HH + h4 * 4];
        acc.x += v0.x + v1.x + v2.x + v3.x;
        acc.y += v0.y + v1.y + v2.y + v3.y;
        acc.z += v0.z + v1.z + v2.z + v3.z;
        acc.w += v0.w + v1.w + v2.w + v3.w;
    }
    for (; r < 25; r++) {
        float4 v = *(const float4*)&base[(size_t)r * HH + h4 * 4];
        acc.x += v.x; acc.y += v.y; acc.z += v.z; acc.w += v.w;
    }
    *(float4*)&g_vispart[(size_t)(b * 4 + part) * HH + h4 * 4] = acc;
}

// ---------------------------------------------------------------------------
// Kernel: segment means -> bf16 hi/lo. One block per (b, s), 192 threads.
// ---------------------------------------------------------------------------
__global__ __launch_bounds__(192) void agg_kernel(const float* __restrict__ feat,
                                                  const int* __restrict__ mask) {
    int blk = blockIdx.x;
    int b = blk / SS;
    int s = blk % SS;

    __shared__ int s_list[TT];
    __shared__ int s_cnt;
    if (threadIdx.x == 0) s_cnt = 0;
    __syncthreads();

    const int* mrow = mask + (size_t)b * TT;
    for (int t = threadIdx.x; t < TT; t += 192) {
        if (mrow[t] == s + 1) {
            int pos = atomicAdd(&s_cnt, 1);
            s_list[pos] = t;
        }
    }
    __syncthreads();

    int cnt = s_cnt;
    float inv = (cnt > 0) ? (1.0f / (float)cnt) : 0.0f;

    const float* base = feat + ((size_t)b * ROWSTRIDE + NVV) * HH;
    int h4 = threadIdx.x;                       // 0..191
    float4 acc = make_float4(0.f, 0.f, 0.f, 0.f);
    int i = 0;
    for (; i + 4 <= cnt; i += 4) {
        float4 v0 = *(const float4*)&base[(size_t)s_list[i + 0] * HH + h4 * 4];
        float4 v1 = *(const float4*)&base[(size_t)s_list[i + 1] * HH + h4 * 4];
        float4 v2 = *(const float4*)&base[(size_t)s_list[i + 2] * HH + h4 * 4];
        float4 v3 = *(const float4*)&base[(size_t)s_list[i + 3] * HH + h4 * 4];
        acc.x += v0.x + v1.x + v2.x + v3.x;
        acc.y += v0.y + v1.y + v2.y + v3.y;
        acc.z += v0.z + v1.z + v2.z + v3.z;
        acc.w += v0.w + v1.w + v2.w + v3.w;
    }
    for (; i < cnt; i++) {
        float4 v = *(const float4*)&base[(size_t)s_list[i] * HH + h4 * 4];
        acc.x += v.x; acc.y += v.y; acc.z += v.z; acc.w += v.w;
    }
    acc.x *= inv; acc.y *= inv; acc.z *= inv; acc.w *= inv;

    ushort4 hh, ll;
    split1(acc.x, hh.x, ll.x); split1(acc.y, hh.y, ll.y);
    split1(acc.z, hh.z, ll.z); split1(acc.w, hh.w, ll.w);
    size_t o = (size_t)blk * HH + h4 * 4;
    *(ushort4*)&g_ahi[o] = hh;
    *(ushort4*)&g_alo[o] = ll;
}

// ---------------------------------------------------------------------------
// Kernel: split W1 (w[:, :768]) into bf16 hi/lo
// ---------------------------------------------------------------------------
__global__ __launch_bounds__(256) void wconv_kernel(const float* __restrict__ w) {
    int idx = blockIdx.x * 256 + threadIdx.x;   // float4 index
    if (idx >= HH * HH / 4) return;
    int n = idx / (HH / 4);
    int k4 = idx % (HH / 4);
    float4 v = *(const float4*)&w[(size_t)n * K2 + k4 * 4];
    ushort4 hh, ll;
    split1(v.x, hh.x, ll.x); split1(v.y, hh.y, ll.y);
    split1(v.z, hh.z, ll.z); split1(v.w, hh.w, ll.w);
    size_t o = (size_t)n * HH + k4 * 4;
    *(ushort4*)&g_w1h[o] = hh;
    *(ushort4*)&g_w1l[o] = ll;
}

// ---------------------------------------------------------------------------
// Kernel: g_v2[b][n] = vision_mean[b] . W2[n] + bias[n].  grid (32, 6), 256 thr.
// ---------------------------------------------------------------------------
__global__ __launch_bounds__(256) void v2_kernel(const float* __restrict__ w,
                                                 const float* __restrict__ bias) {
    int b = blockIdx.x;
    int n0 = blockIdx.y * 128;
    __shared__ float sv[HH];
    __shared__ float red[256];

    for (int h = threadIdx.x; h < HH; h += 256) {
        float t = g_vispart[(size_t)(b * 4 + 0) * HH + h]
                + g_vispart[(size_t)(b * 4 + 1) * HH + h]
                + g_vispart[(size_t)(b * 4 + 2) * HH + h]
                + g_vispart[(size_t)(b * 4 + 3) * HH + h];
        sv[h] = t * (1.0f / (float)NVV);
    }
    __syncthreads();

    int n = n0 + (threadIdx.x & 127);
    int half = threadIdx.x >> 7;                // 0 or 1
    const float* wr = w + (size_t)n * K2 + HH + half * 384;
    const float* svp = sv + half * 384;
    float acc = 0.f;
    #pragma unroll 4
    for (int k = 0; k < 384; k += 4) {
        float4 wv = *(const float4*)&wr[k];
        acc += svp[k] * wv.x + svp[k + 1] * wv.y + svp[k + 2] * wv.z + svp[k + 3] * wv.w;
    }
    red[threadIdx.x] = acc;
    __syncthreads();
    if (half == 0)
        g_v2[(size_t)b * HH + n] = red[threadIdx.x] + red[threadIdx.x + 128] + bias[n];
}

// ---------------------------------------------------------------------------
// Kernel: mma.sync bf16-split GEMM (HMMA; no sm_100a-only features).
// out[m][n] = sum_k agg[m][k]*W1[n][k] + g_v2[m/S][n]
// BM=128, BN=128, BK=32, 24 cp.async double-buffered stages.
// 8 warps: 2 (m) x 4 (n); warp tile 64x32; D = Ah.Bh + Ah.Bl + Al.Bh (fp32 acc).
// ---------------------------------------------------------------------------
#define NSTG 24
#define ROWH 40                       // padded row length in halfs (80 B)
#define STGH (128 * ROWH)             // halfs per stage per array (5120)
#define ARRH (2 * STGH)               // halfs per array (both stages)
#define GEMM_SMEM (4 * ARRH * 2)      // bytes = 81920

__global__ __launch_bounds__(256) void gemm_kernel(float* __restrict__ out) {
    extern __shared__ unsigned short sm[];
    unsigned short* sAh = sm;
    unsigned short* sAl = sAh + ARRH;
    unsigned short* sBh = sAl + ARRH;
    unsigned short* sBl = sBh + ARRH;

    const int tid = threadIdx.x;
    const int lane = tid & 31;
    const int wid = tid >> 5;
    const int wm = wid >> 2;          // 0..1 -> m offset wm*64
    const int wn = wid & 3;           // 0..3 -> n offset wn*32
    const int n0 = blockIdx.x * 128;
    const int m0 = blockIdx.y * 128;

    float acc[4][4][4];
    #pragma unroll
    for (int i = 0; i < 4; i++)
        #pragma unroll
        for (int j = 0; j < 4; j++)
            #pragma unroll
            for (int r = 0; r < 4; r++) acc[i][j][r] = 0.f;

    // cp.async stage issue: 512 16B-chunks per array; 2 per thread per array.
    auto issue_stage = [&](int s, int buf) {
        const int k0 = s * 32;
        #pragma unroll
        for (int j = 0; j < 2; j++) {
            int idx = tid + j * 256;          // 0..511
            int row = idx >> 2;               // 0..127
            int c16 = idx & 3;                // 16B chunk within row
            int kk = k0 + c16 * 8;
            uint32_t soff = (uint32_t)(buf * STGH + row * ROWH + c16 * 8) * 2u;
            size_t ga = (size_t)(m0 + row) * HH + kk;
            size_t gb = (size_t)(n0 + row) * HH + kk;
            cpasync16(smem_u32(sAh) + soff, &g_ahi[ga]);
            cpasync16(smem_u32(sAl) + soff, &g_alo[ga]);
            cpasync16(smem_u32(sBh) + soff, &g_w1h[gb]);
            cpasync16(smem_u32(sBl) + soff, &g_w1l[gb]);
        }
        CP_COMMIT();
    };

    issue_stage(0, 0);
    issue_stage(1, 1);

    const uint32_t bAh = smem_u32(sAh), bAl = smem_u32(sAl);
    const uint32_t bBh = smem_u32(sBh), bBl = smem_u32(sBl);

    for (int s = 0; s < NSTG; s++) {
        if (s == NSTG - 1) asm volatile("cp.async.wait_group 0;" ::: "memory");
        else               asm volatile("cp.async.wait_group 1;" ::: "memory");
        __syncthreads();

        const int buf = s & 1;
        const uint32_t stg = (uint32_t)(buf * STGH) * 2u;

        #pragma unroll
        for (int ks = 0; ks < 2; ks++) {
            const int kh = ks * 16;
            uint32_t a_h[4][4], a_l[4][4], b_h[4][2], b_l[4][2];

            // A fragments: rows (lane&15), k col (lane>>4)*8
            #pragma unroll
            for (int ti = 0; ti < 4; ti++) {
                int mr = wm * 64 + ti * 16 + (lane & 15);
                uint32_t off = stg + (uint32_t)(mr * ROWH + kh + (lane >> 4) * 8) * 2u;
                ldsm_x4(a_h[ti], bAh + off);
                ldsm_x4(a_l[ti], bAl + off);
            }
            // B fragments: rows (lane&7), k col ((lane>>3)&1)*8 (lanes 0-15 used)
            #pragma unroll
            for (int tj = 0; tj < 4; tj++) {
                int nr = wn * 32 + tj * 8 + (lane & 7);
                uint32_t off = stg + (uint32_t)(nr * ROWH + kh + ((lane >> 3) & 1) * 8) * 2u;
                ldsm_x2(b_h[tj], bBh + off);
                ldsm_x2(b_l[tj], bBl + off);
            }

            #pragma unroll
            for (int ti = 0; ti < 4; ti++)
                #pragma unroll
                for (int tj = 0; tj < 4; tj++) {
                    mma_bf16(acc[ti][tj], a_h[ti], b_h[tj]);
                    mma_bf16(acc[ti][tj], a_h[ti], b_l[tj]);
                    mma_bf16(acc[ti][tj], a_l[ti], b_h[tj]);
                }
        }
        __syncthreads();
        if (s + 2 < NSTG) issue_stage(s + 2, buf);
    }

    // Epilogue: stage fragments into padded fp32 smem tile, then coalesced
    // store with fused v2 broadcast add.
    float* st = (float*)sm;                     // 128 x 129 floats = 66048 B
    const int g = lane >> 2;
    const int t2 = (lane & 3) * 2;
    #pragma unroll
    for (int ti = 0; ti < 4; ti++)
        #pragma unroll
        for (int tj = 0; tj < 4; tj++) {
            int r0 = wm * 64 + ti * 16 + g;
            int c0 = wn * 32 + tj * 8 + t2;
            st[r0 * 129 + c0]         = acc[ti][tj][0];
            st[r0 * 129 + c0 + 1]     = acc[ti][tj][1];
            st[(r0 + 8) * 129 + c0]     = acc[ti][tj][2];
            st[(r0 + 8) * 129 + c0 + 1] = acc[ti][tj][3];
        }
    __syncthreads();

    #pragma unroll 4
    for (int it = 0; it < 64; it++) {
        int q = tid + it * 256;
        int row = q >> 7;
        int col = q & 127;
        int m = m0 + row;
        int b = m / SS;
        out[(size_t)m * HH + n0 + col] = st[row * 129 + col] + g_v2[(size_t)b * HH + n0 + col];
    }
}

// ---------------------------------------------------------------------------
extern "C" void kernel_launch(void* const* d_in, const int* in_sizes, int n_in,
                              void* d_out, int out_size) {
    const float* feat = (const float*)d_in[0];   // (B, NV+T, H) f32
    const int*   mask = (const int*)d_in[1];     // (B, T) i32
    const float* w    = (const float*)d_in[2];   // (H, 2H) f32
    const float* bias = (const float*)d_in[3];   // (H,) f32
    float* out = (float*)d_out;                  // (B, S, H) f32

    vis_part_kernel<<<dim3(BB, 4), 192>>>(feat);
    agg_kernel<<<BSROWS, 192>>>(feat, mask);
    wconv_kernel<<<(HH * HH / 4 + 255) / 256, 256>>>(w);
    v2_kernel<<<dim3(BB, 6), 256>>>(w, bias);

    cudaFuncSetAttribute(gemm_kernel, cudaFuncAttributeMaxDynamicSharedMemorySize, GEMM_SMEM);
    gemm_kernel<<<dim3(HH / 128, BSROWS / 128), 256, GEMM_SMEM>>>(out);
}

// round 6
// speedup vs baseline: 1.9539x; 1.0683x over previous
#include <cuda_runtime.h>
#include <cuda_bf16.h>
#include <stdint.h>

// Problem constants
#define BB 32
#define TT 2000
#define HH 768
#define SS 100
#define NVV 100
#define BSROWS 3200            // B*S
#define ROWSTRIDE 2100         // NV + T
#define K2 1536                // 2*H

// ---------------------------------------------------------------------------
// Scratch (device globals; allocation forbidden)
// ---------------------------------------------------------------------------
__device__ unsigned short g_ahi[BSROWS * HH];   // bf16 hi of segment means
__device__ unsigned short g_alo[BSROWS * HH];   // bf16 lo
__device__ unsigned short g_w1h[HH * HH];       // bf16 hi of W1 (w[:, :768])
__device__ unsigned short g_w1l[HH * HH];
__device__ float g_vispart[BB * 4 * HH];        // partial sums of vision rows
__device__ float g_vis[BB * HH];                // vision mean
__device__ float g_v2[BB * HH];                 // vision @ W2^T + bias

// ---------------------------------------------------------------------------
// Helpers
// ---------------------------------------------------------------------------
__device__ __forceinline__ uint32_t smem_u32(const void* p) {
    uint32_t a;
    asm("{ .reg .u64 t; cvta.to.shared.u64 t, %1; cvt.u32.u64 %0, t; }" : "=r"(a) : "l"(p));
    return a;
}
__device__ __forceinline__ void cpasync16(uint32_t saddr, const void* g) {
    asm volatile("cp.async.cg.shared.global [%0], [%1], 16;" :: "r"(saddr), "l"(g));
}
#define CP_COMMIT() asm volatile("cp.async.commit_group;" ::: "memory")

__device__ __forceinline__ void ldsm_x4(uint32_t* r, uint32_t addr) {
    asm volatile("ldmatrix.sync.aligned.m8n8.x4.shared.b16 {%0,%1,%2,%3}, [%4];"
                 : "=r"(r[0]), "=r"(r[1]), "=r"(r[2]), "=r"(r[3]) : "r"(addr));
}
__device__ __forceinline__ void ldsm_x2(uint32_t* r, uint32_t addr) {
    asm volatile("ldmatrix.sync.aligned.m8n8.x2.shared.b16 {%0,%1}, [%2];"
                 : "=r"(r[0]), "=r"(r[1]) : "r"(addr));
}
__device__ __forceinline__ void mma_bf16(float* c, const uint32_t* a, const uint32_t* b) {
    asm volatile("mma.sync.aligned.m16n8k16.row.col.f32.bf16.bf16.f32 "
                 "{%0,%1,%2,%3}, {%4,%5,%6,%7}, {%8,%9}, {%0,%1,%2,%3};"
                 : "+f"(c[0]), "+f"(c[1]), "+f"(c[2]), "+f"(c[3])
                 : "r"(a[0]), "r"(a[1]), "r"(a[2]), "r"(a[3]), "r"(b[0]), "r"(b[1]));
}

// bf16 hi/lo split
__device__ __forceinline__ void split1(float x, unsigned short& h, unsigned short& l) {
    __nv_bfloat16 bh = __float2bfloat16_rn(x);
    h = __bfloat16_as_ushort(bh);
    l = __bfloat16_as_ushort(__float2bfloat16_rn(x - __bfloat162float(bh)));
}

// ---------------------------------------------------------------------------
// Kernel: vision partial sums. grid (32, 4), 192 threads. Each block sums 25 rows.
// ---------------------------------------------------------------------------
__global__ __launch_bounds__(192) void vis_part_kernel(const float* __restrict__ feat) {
    int b = blockIdx.x, part = blockIdx.y;
    const float* base = feat + ((size_t)b * ROWSTRIDE + part * 25) * HH;
    int h4 = threadIdx.x;                      // 0..191
    float4 acc = make_float4(0.f, 0.f, 0.f, 0.f);
    int r = 0;
    for (; r + 4 <= 25; r += 4) {
        float4 v0 = *(const float4*)&base[(size_t)(r + 0) * HH + h4 * 4];
        float4 v1 = *(const float4*)&base[(size_t)(r + 1) * HH + h4 * 4];
        float4 v2 = *(const float4*)&base[(size_t)(r + 2) * HH + h4 * 4];
        float4 v3 = *(const float4*)&base[(size_t)(r + 3) * HH + h4 * 4];
        acc.x += v0.x + v1.x + v2.x + v3.x;
        acc.y += v0.y + v1.y + v2.y + v3.y;
        acc.z += v0.z + v1.z + v2.z + v3.z;
        acc.w += v0.w + v1.w + v2.w + v3.w;
    }
    for (; r < 25; r++) {
        float4 v = *(const float4*)&base[(size_t)r * HH + h4 * 4];
        acc.x += v.x; acc.y += v.y; acc.z += v.z; acc.w += v.w;
    }
    *(float4*)&g_vispart[(size_t)(b * 4 + part) * HH + h4 * 4] = acc;
}

// ---------------------------------------------------------------------------
// Kernel: finalize vision mean. grid 32, 192 threads.
// ---------------------------------------------------------------------------
__global__ __launch_bounds__(192) void vis_fin_kernel() {
    int b = blockIdx.x, h4 = threadIdx.x;
    float4 p0 = *(const float4*)&g_vispart[(size_t)(b * 4 + 0) * HH + h4 * 4];
    float4 p1 = *(const float4*)&g_vispart[(size_t)(b * 4 + 1) * HH + h4 * 4];
    float4 p2 = *(const float4*)&g_vispart[(size_t)(b * 4 + 2) * HH + h4 * 4];
    float4 p3 = *(const float4*)&g_vispart[(size_t)(b * 4 + 3) * HH + h4 * 4];
    const float inv = 1.0f / (float)NVV;
    float4 o;
    o.x = (p0.x + p1.x + p2.x + p3.x) * inv;
    o.y = (p0.y + p1.y + p2.y + p3.y) * inv;
    o.z = (p0.z + p1.z + p2.z + p3.z) * inv;
    o.w = (p0.w + p1.w + p2.w + p3.w) * inv;
    *(float4*)&g_vis[(size_t)b * HH + h4 * 4] = o;
}

// ---------------------------------------------------------------------------
// Kernel: segment means -> bf16 hi/lo. One block per (b, s), 192 threads.
// ---------------------------------------------------------------------------
__global__ __launch_bounds__(192) void agg_kernel(const float* __restrict__ feat,
                                                  const int* __restrict__ mask) {
    int blk = blockIdx.x;
    int b = blk / SS;
    int s = blk % SS;

    __shared__ int s_list[TT];
    __shared__ int s_cnt;
    if (threadIdx.x == 0) s_cnt = 0;
    __syncthreads();

    const int* mrow = mask + (size_t)b * TT;
    for (int t = threadIdx.x; t < TT; t += 192) {
        if (mrow[t] == s + 1) {
            int pos = atomicAdd(&s_cnt, 1);
            s_list[pos] = t;
        }
    }
    __syncthreads();

    int cnt = s_cnt;
    float inv = (cnt > 0) ? (1.0f / (float)cnt) : 0.0f;

    const float* base = feat + ((size_t)b * ROWSTRIDE + NVV) * HH;
    int h4 = threadIdx.x;                       // 0..191
    float4 acc = make_float4(0.f, 0.f, 0.f, 0.f);
    int i = 0;
    for (; i + 8 <= cnt; i += 8) {              // 8 independent loads -> MLP 8
        float4 v[8];
        #pragma unroll
        for (int j = 0; j < 8; j++)
            v[j] = *(const float4*)&base[(size_t)s_list[i + j] * HH + h4 * 4];
        #pragma unroll
        for (int j = 0; j < 8; j++) {
            acc.x += v[j].x; acc.y += v[j].y; acc.z += v[j].z; acc.w += v[j].w;
        }
    }
    for (; i + 4 <= cnt; i += 4) {
        float4 v[4];
        #pragma unroll
        for (int j = 0; j < 4; j++)
            v[j] = *(const float4*)&base[(size_t)s_list[i + j] * HH + h4 * 4];
        #pragma unroll
        for (int j = 0; j < 4; j++) {
            acc.x += v[j].x; acc.y += v[j].y; acc.z += v[j].z; acc.w += v[j].w;
        }
    }
    for (; i < cnt; i++) {
        float4 v = *(const float4*)&base[(size_t)s_list[i] * HH + h4 * 4];
        acc.x += v.x; acc.y += v.y; acc.z += v.z; acc.w += v.w;
    }
    acc.x *= inv; acc.y *= inv; acc.z *= inv; acc.w *= inv;

    ushort4 hh, ll;
    split1(acc.x, hh.x, ll.x); split1(acc.y, hh.y, ll.y);
    split1(acc.z, hh.z, ll.z); split1(acc.w, hh.w, ll.w);
    size_t o = (size_t)blk * HH + h4 * 4;
    *(ushort4*)&g_ahi[o] = hh;
    *(ushort4*)&g_alo[o] = ll;
}

// ---------------------------------------------------------------------------
// Kernel: split W1 (w[:, :768]) into bf16 hi/lo
// ---------------------------------------------------------------------------
__global__ __launch_bounds__(256) void wconv_kernel(const float* __restrict__ w) {
    int idx = blockIdx.x * 256 + threadIdx.x;   // float4 index
    if (idx >= HH * HH / 4) return;
    int n = idx / (HH / 4);
    int k4 = idx % (HH / 4);
    float4 v = *(const float4*)&w[(size_t)n * K2 + k4 * 4];
    ushort4 hh, ll;
    split1(v.x, hh.x, ll.x); split1(v.y, hh.y, ll.y);
    split1(v.z, hh.z, ll.z); split1(v.w, hh.w, ll.w);
    size_t o = (size_t)n * HH + k4 * 4;
    *(ushort4*)&g_w1h[o] = hh;
    *(ushort4*)&g_w1l[o] = ll;
}

// ---------------------------------------------------------------------------
// Kernel: g_v2[b][n] = vision_mean[b] . W2[n] + bias[n].
// Warp-per-n, 4 batches per warp. grid (96, 8), 256 threads.
// ---------------------------------------------------------------------------
__global__ __launch_bounds__(256) void v2_kernel(const float* __restrict__ w,
                                                 const float* __restrict__ bias) {
    const int lane = threadIdx.x & 31;
    const int wid = threadIdx.x >> 5;
    const int n = blockIdx.x * 8 + wid;         // 0..767
    const int b0 = blockIdx.y * 4;              // 0,4,...,28

    const float* wr = w + (size_t)n * K2 + HH;  // W2 row n
    float a0 = 0.f, a1 = 0.f, a2 = 0.f, a3 = 0.f;
    #pragma unroll
    for (int i = 0; i < 6; i++) {
        int k4 = i * 32 + lane;                 // float4 index, coalesced
        float4 wv = *(const float4*)&wr[k4 * 4];
        float4 s0 = *(const float4*)&g_vis[(size_t)(b0 + 0) * HH + k4 * 4];
        float4 s1 = *(const float4*)&g_vis[(size_t)(b0 + 1) * HH + k4 * 4];
        float4 s2 = *(const float4*)&g_vis[(size_t)(b0 + 2) * HH + k4 * 4];
        float4 s3 = *(const float4*)&g_vis[(size_t)(b0 + 3) * HH + k4 * 4];
        a0 += s0.x * wv.x + s0.y * wv.y + s0.z * wv.z + s0.w * wv.w;
        a1 += s1.x * wv.x + s1.y * wv.y + s1.z * wv.z + s1.w * wv.w;
        a2 += s2.x * wv.x + s2.y * wv.y + s2.z * wv.z + s2.w * wv.w;
        a3 += s3.x * wv.x + s3.y * wv.y + s3.z * wv.z + s3.w * wv.w;
    }
    #pragma unroll
    for (int off = 16; off; off >>= 1) {
        a0 += __shfl_xor_sync(0xFFFFFFFFu, a0, off);
        a1 += __shfl_xor_sync(0xFFFFFFFFu, a1, off);
        a2 += __shfl_xor_sync(0xFFFFFFFFu, a2, off);
        a3 += __shfl_xor_sync(0xFFFFFFFFu, a3, off);
    }
    if (lane == 0) {
        float bb = bias[n];
        g_v2[(size_t)(b0 + 0) * HH + n] = a0 + bb;
        g_v2[(size_t)(b0 + 1) * HH + n] = a1 + bb;
        g_v2[(size_t)(b0 + 2) * HH + n] = a2 + bb;
        g_v2[(size_t)(b0 + 3) * HH + n] = a3 + bb;
    }
}

// ---------------------------------------------------------------------------
// Kernel: mma.sync bf16-split GEMM, 3-stage cp.async pipeline.
// out[m][n] = sum_k agg[m][k]*W1[n][k] + g_v2[m/S][n]
// BM=128, BN=128, BK=32, NSTG=24 stages, 3 smem buffers, 1 sync/stage.
// 8 warps: 2 (m) x 4 (n); warp tile 64x32; D = Ah.Bh + Ah.Bl + Al.Bh (fp32 acc).
// ---------------------------------------------------------------------------
#define NSTG 24
#define NBUF 3
#define ROWH 40                       // padded row length in halfs (80 B)
#define STGH (128 * ROWH)             // halfs per stage per array (5120)
#define ARRH (NBUF * STGH)            // halfs per array
#define GEMM_SMEM (4 * ARRH * 2)      // bytes = 122880

__global__ __launch_bounds__(256) void gemm_kernel(float* __restrict__ out) {
    extern __shared__ unsigned short sm[];
    unsigned short* sAh = sm;
    unsigned short* sAl = sAh + ARRH;
    unsigned short* sBh = sAl + ARRH;
    unsigned short* sBl = sBh + ARRH;

    const int tid = threadIdx.x;
    const int lane = tid & 31;
    const int wid = tid >> 5;
    const int wm = wid >> 2;          // 0..1 -> m offset wm*64
    const int wn = wid & 3;           // 0..3 -> n offset wn*32
    const int n0 = blockIdx.x * 128;
    const int m0 = blockIdx.y * 128;

    const uint32_t bAh = smem_u32(sAh), bAl = smem_u32(sAl);
    const uint32_t bBh = smem_u32(sBh), bBl = smem_u32(sBl);

    float acc[4][4][4];
    #pragma unroll
    for (int i = 0; i < 4; i++)
        #pragma unroll
        for (int j = 0; j < 4; j++)
            #pragma unroll
            for (int r = 0; r < 4; r++) acc[i][j][r] = 0.f;

    auto issue_stage = [&](int s, int buf) {
        const int k0 = s * 32;
        #pragma unroll
        for (int j = 0; j < 2; j++) {
            int idx = tid + j * 256;          // 0..511
            int row = idx >> 2;               // 0..127
            int c16 = idx & 3;                // 16B chunk within row
            int kk = k0 + c16 * 8;
            uint32_t soff = (uint32_t)(buf * STGH + row * ROWH + c16 * 8) * 2u;
            size_t ga = (size_t)(m0 + row) * HH + kk;
            size_t gb = (size_t)(n0 + row) * HH + kk;
            cpasync16(bAh + soff, &g_ahi[ga]);
            cpasync16(bAl + soff, &g_alo[ga]);
            cpasync16(bBh + soff, &g_w1h[gb]);
            cpasync16(bBl + soff, &g_w1l[gb]);
        }
        CP_COMMIT();
    };

    issue_stage(0, 0);
    issue_stage(1, 1);

    for (int s = 0; s < NSTG; s++) {
        if (s == NSTG - 1) asm volatile("cp.async.wait_group 0;" ::: "memory");
        else               asm volatile("cp.async.wait_group 1;" ::: "memory");
        __syncthreads();

        // prefetch stage s+2 into the buffer freed by stage s-1
        if (s + 2 < NSTG) issue_stage(s + 2, (s + 2) % NBUF);

        const int buf = s % NBUF;
        const uint32_t stg = (uint32_t)(buf * STGH) * 2u;

        #pragma unroll
        for (int ks = 0; ks < 2; ks++) {
            const int kh = ks * 16;
            uint32_t a_h[4][4], a_l[4][4], b_h[4][2], b_l[4][2];

            #pragma unroll
            for (int ti = 0; ti < 4; ti++) {
                int mr = wm * 64 + ti * 16 + (lane & 15);
                uint32_t off = stg + (uint32_t)(mr * ROWH + kh + (lane >> 4) * 8) * 2u;
                ldsm_x4(a_h[ti], bAh + off);
                ldsm_x4(a_l[ti], bAl + off);
            }
            #pragma unroll
            for (int tj = 0; tj < 4; tj++) {
                int nr = wn * 32 + tj * 8 + (lane & 7);
                uint32_t off = stg + (uint32_t)(nr * ROWH + kh + ((lane >> 3) & 1) * 8) * 2u;
                ldsm_x2(b_h[tj], bBh + off);
                ldsm_x2(b_l[tj], bBl + off);
            }

            #pragma unroll
            for (int ti = 0; ti < 4; ti++)
                #pragma unroll
                for (int tj = 0; tj < 4; tj++) {
                    mma_bf16(acc[ti][tj], a_h[ti], b_h[tj]);
                    mma_bf16(acc[ti][tj], a_h[ti], b_l[tj]);
                    mma_bf16(acc[ti][tj], a_l[ti], b_h[tj]);
                }
        }
    }
    __syncthreads();   // all warps done before smem reuse

    // Epilogue: fragments -> padded fp32 smem tile -> coalesced store + v2 add.
    float* st = (float*)sm;                     // 128 x 129 floats = 66048 B
    const int g = lane >> 2;
    const int t2 = (lane & 3) * 2;
    #pragma unroll
    for (int ti = 0; ti < 4; ti++)
        #pragma unroll
        for (int tj = 0; tj < 4; tj++) {
            int r0 = wm * 64 + ti * 16 + g;
            int c0 = wn * 32 + tj * 8 + t2;
            st[r0 * 129 + c0]           = acc[ti][tj][0];
            st[r0 * 129 + c0 + 1]       = acc[ti][tj][1];
            st[(r0 + 8) * 129 + c0]     = acc[ti][tj][2];
            st[(r0 + 8) * 129 + c0 + 1] = acc[ti][tj][3];
        }
    __syncthreads();

    #pragma unroll 4
    for (int it = 0; it < 64; it++) {
        int q = tid + it * 256;
        int row = q >> 7;
        int col = q & 127;
        int m = m0 + row;
        int b = m / SS;
        out[(size_t)m * HH + n0 + col] = st[row * 129 + col] + g_v2[(size_t)b * HH + n0 + col];
    }
}

// ---------------------------------------------------------------------------
extern "C" void kernel_launch(void* const* d_in, const int* in_sizes, int n_in,
                              void* d_out, int out_size) {
    const float* feat = (const float*)d_in[0];   // (B, NV+T, H) f32
    const int*   mask = (const int*)d_in[1];     // (B, T) i32
    const float* w    = (const float*)d_in[2];   // (H, 2H) f32
    const float* bias = (const float*)d_in[3];   // (H,) f32
    float* out = (float*)d_out;                  // (B, S, H) f32

    vis_part_kernel<<<dim3(BB, 4), 192>>>(feat);
    vis_fin_kernel<<<BB, 192>>>();
    agg_kernel<<<BSROWS, 192>>>(feat, mask);
    wconv_kernel<<<(HH * HH / 4 + 255) / 256, 256>>>(w);
    v2_kernel<<<dim3(96, 8), 256>>>(w, bias);

    cudaFuncSetAttribute(gemm_kernel, cudaFuncAttributeMaxDynamicSharedMemorySize, GEMM_SMEM);
    gemm_kernel<<<dim3(HH / 128, BSROWS / 128), 256, GEMM_SMEM>>>(out);
}

// round 8
// speedup vs baseline: 2.5273x; 1.2935x over previous
#include <cuda_runtime.h>
#include <cuda_bf16.h>
#include <stdint.h>

// Problem constants
#define BB 32
#define TT 2000
#define HH 768
#define SS 100
#define NVV 100
#define BSROWS 3200            // B*S
#define ROWSTRIDE 2100         // NV + T
#define K2 1536                // 2*H

// ---------------------------------------------------------------------------
// Scratch (device globals; allocation forbidden)
// ---------------------------------------------------------------------------
__device__ unsigned short g_ahi[BSROWS * HH];   // bf16 hi of segment means
__device__ unsigned short g_alo[BSROWS * HH];   // bf16 lo
__device__ unsigned short g_w1h[HH * HH];       // bf16 hi of W1 (w[:, :768])
__device__ unsigned short g_w1l[HH * HH];
__device__ float g_vispart[BB * 4 * HH];        // partial sums of vision rows
__device__ float g_vis[BB * HH];                // vision mean
__device__ float g_v2[BB * HH];                 // vision @ W2^T + bias

// ---------------------------------------------------------------------------
// Helpers
// ---------------------------------------------------------------------------
__device__ __forceinline__ uint32_t smem_u32(const void* p) {
    uint32_t a;
    asm("{ .reg .u64 t; cvta.to.shared.u64 t, %1; cvt.u32.u64 %0, t; }" : "=r"(a) : "l"(p));
    return a;
}
__device__ __forceinline__ void cpasync16(uint32_t saddr, const void* g) {
    asm volatile("cp.async.cg.shared.global [%0], [%1], 16;" :: "r"(saddr), "l"(g));
}
#define CP_COMMIT() asm volatile("cp.async.commit_group;" ::: "memory")

__device__ __forceinline__ void ldsm_x4(uint32_t* r, uint32_t addr) {
    asm volatile("ldmatrix.sync.aligned.m8n8.x4.shared.b16 {%0,%1,%2,%3}, [%4];"
                 : "=r"(r[0]), "=r"(r[1]), "=r"(r[2]), "=r"(r[3]) : "r"(addr));
}
__device__ __forceinline__ void ldsm_x2(uint32_t* r, uint32_t addr) {
    asm volatile("ldmatrix.sync.aligned.m8n8.x2.shared.b16 {%0,%1}, [%2];"
                 : "=r"(r[0]), "=r"(r[1]) : "r"(addr));
}
__device__ __forceinline__ void mma_bf16(float* c, const uint32_t* a, const uint32_t* b) {
    asm volatile("mma.sync.aligned.m16n8k16.row.col.f32.bf16.bf16.f32 "
                 "{%0,%1,%2,%3}, {%4,%5,%6,%7}, {%8,%9}, {%0,%1,%2,%3};"
                 : "+f"(c[0]), "+f"(c[1]), "+f"(c[2]), "+f"(c[3])
                 : "r"(a[0]), "r"(a[1]), "r"(a[2]), "r"(a[3]), "r"(b[0]), "r"(b[1]));
}

// bf16 hi/lo split
__device__ __forceinline__ void split1(float x, unsigned short& h, unsigned short& l) {
    __nv_bfloat16 bh = __float2bfloat16_rn(x);
    h = __bfloat16_as_ushort(bh);
    l = __bfloat16_as_ushort(__float2bfloat16_rn(x - __bfloat162float(bh)));
}

// ---------------------------------------------------------------------------
// Kernel: vision partial sums. grid (32, 4), 192 threads. Each block sums 25 rows.
// ---------------------------------------------------------------------------
__global__ __launch_bounds__(192) void vis_part_kernel(const float* __restrict__ feat) {
    int b = blockIdx.x, part = blockIdx.y;
    const float* base = feat + ((size_t)b * ROWSTRIDE + part * 25) * HH;
    int h4 = threadIdx.x;                      // 0..191
    float4 acc = make_float4(0.f, 0.f, 0.f, 0.f);
    int r = 0;
    for (; r + 4 <= 25; r += 4) {
        float4 v0 = *(const float4*)&base[(size_t)(r + 0) * HH + h4 * 4];
        float4 v1 = *(const float4*)&base[(size_t)(r + 1) * HH + h4 * 4];
        float4 v2 = *(const float4*)&base[(size_t)(r + 2) * HH + h4 * 4];
        float4 v3 = *(const float4*)&base[(size_t)(r + 3) * HH + h4 * 4];
        acc.x += v0.x + v1.x + v2.x + v3.x;
        acc.y += v0.y + v1.y + v2.y + v3.y;
        acc.z += v0.z + v1.z + v2.z + v3.z;
        acc.w += v0.w + v1.w + v2.w + v3.w;
    }
    for (; r < 25; r++) {
        float4 v = *(const float4*)&base[(size_t)r * HH + h4 * 4];
        acc.x += v.x; acc.y += v.y; acc.z += v.z; acc.w += v.w;
    }
    *(float4*)&g_vispart[(size_t)(b * 4 + part) * HH + h4 * 4] = acc;
}

// ---------------------------------------------------------------------------
// Kernel: finalize vision mean. grid 32, 192 threads.
// ---------------------------------------------------------------------------
__global__ __launch_bounds__(192) void vis_fin_kernel() {
    int b = blockIdx.x, h4 = threadIdx.x;
    float4 p0 = *(const float4*)&g_vispart[(size_t)(b * 4 + 0) * HH + h4 * 4];
    float4 p1 = *(const float4*)&g_vispart[(size_t)(b * 4 + 1) * HH + h4 * 4];
    float4 p2 = *(const float4*)&g_vispart[(size_t)(b * 4 + 2) * HH + h4 * 4];
    float4 p3 = *(const float4*)&g_vispart[(size_t)(b * 4 + 3) * HH + h4 * 4];
    const float inv = 1.0f / (float)NVV;
    float4 o;
    o.x = (p0.x + p1.x + p2.x + p3.x) * inv;
    o.y = (p0.y + p1.y + p2.y + p3.y) * inv;
    o.z = (p0.z + p1.z + p2.z + p3.z) * inv;
    o.w = (p0.w + p1.w + p2.w + p3.w) * inv;
    *(float4*)&g_vis[(size_t)b * HH + h4 * 4] = o;
}

// ---------------------------------------------------------------------------
// Kernel: segment means -> bf16 hi/lo. One block per (b, s), 192 threads.
// ---------------------------------------------------------------------------
__global__ __launch_bounds__(192) void agg_kernel(const float* __restrict__ feat,
                                                  const int* __restrict__ mask) {
    int blk = blockIdx.x;
    int b = blk / SS;
    int s = blk % SS;

    __shared__ int s_list[TT];
    __shared__ int s_cnt;
    if (threadIdx.x == 0) s_cnt = 0;
    __syncthreads();

    const int* mrow = mask + (size_t)b * TT;
    for (int t = threadIdx.x; t < TT; t += 192) {
        if (mrow[t] == s + 1) {
            int pos = atomicAdd(&s_cnt, 1);
            s_list[pos] = t;
        }
    }
    __syncthreads();

    int cnt = s_cnt;
    float inv = (cnt > 0) ? (1.0f / (float)cnt) : 0.0f;

    const float* base = feat + ((size_t)b * ROWSTRIDE + NVV) * HH;
    int h4 = threadIdx.x;                       // 0..191
    float4 acc = make_float4(0.f, 0.f, 0.f, 0.f);
    int i = 0;
    for (; i + 8 <= cnt; i += 8) {              // 8 independent loads -> MLP 8
        float4 v[8];
        #pragma unroll
        for (int j = 0; j < 8; j++)
            v[j] = *(const float4*)&base[(size_t)s_list[i + j] * HH + h4 * 4];
        #pragma unroll
        for (int j = 0; j < 8; j++) {
            acc.x += v[j].x; acc.y += v[j].y; acc.z += v[j].z; acc.w += v[j].w;
        }
    }
    for (; i + 4 <= cnt; i += 4) {
        float4 v[4];
        #pragma unroll
        for (int j = 0; j < 4; j++)
            v[j] = *(const float4*)&base[(size_t)s_list[i + j] * HH + h4 * 4];
        #pragma unroll
        for (int j = 0; j < 4; j++) {
            acc.x += v[j].x; acc.y += v[j].y; acc.z += v[j].z; acc.w += v[j].w;
        }
    }
    for (; i < cnt; i++) {
        float4 v = *(const float4*)&base[(size_t)s_list[i] * HH + h4 * 4];
        acc.x += v.x; acc.y += v.y; acc.z += v.z; acc.w += v.w;
    }
    acc.x *= inv; acc.y *= inv; acc.z *= inv; acc.w *= inv;

    ushort4 hh, ll;
    split1(acc.x, hh.x, ll.x); split1(acc.y, hh.y, ll.y);
    split1(acc.z, hh.z, ll.z); split1(acc.w, hh.w, ll.w);
    size_t o = (size_t)blk * HH + h4 * 4;
    *(ushort4*)&g_ahi[o] = hh;
    *(ushort4*)&g_alo[o] = ll;
}

// ---------------------------------------------------------------------------
// Kernel: split W1 (w[:, :768]) into bf16 hi/lo. 2 float4s per thread (MLP 2).
// ---------------------------------------------------------------------------
__global__ __launch_bounds__(256) void wconv_kernel(const float* __restrict__ w) {
    int i0 = blockIdx.x * 512 + threadIdx.x;    // float4 index
    #pragma unroll
    for (int j = 0; j < 2; j++) {
        int idx = i0 + j * 256;
        int n = idx / (HH / 4);
        int k4 = idx % (HH / 4);
        float4 v = *(const float4*)&w[(size_t)n * K2 + k4 * 4];
        ushort4 hh, ll;
        split1(v.x, hh.x, ll.x); split1(v.y, hh.y, ll.y);
        split1(v.z, hh.z, ll.z); split1(v.w, hh.w, ll.w);
        size_t o = (size_t)n * HH + k4 * 4;
        *(ushort4*)&g_w1h[o] = hh;
        *(ushort4*)&g_w1l[o] = ll;
    }
}

// ---------------------------------------------------------------------------
// Kernel: g_v2[b][n] = vision_mean[b] . W2[n] + bias[n].
// Warp-per-n, 4 batches per warp. grid (96, 8), 256 threads.
// ---------------------------------------------------------------------------
__global__ __launch_bounds__(256) void v2_kernel(const float* __restrict__ w,
                                                 const float* __restrict__ bias) {
    const int lane = threadIdx.x & 31;
    const int wid = threadIdx.x >> 5;
    const int n = blockIdx.x * 8 + wid;         // 0..767
    const int b0 = blockIdx.y * 4;              // 0,4,...,28

    const float* wr = w + (size_t)n * K2 + HH;  // W2 row n
    float a0 = 0.f, a1 = 0.f, a2 = 0.f, a3 = 0.f;
    #pragma unroll
    for (int i = 0; i < 6; i++) {
        int k4 = i * 32 + lane;                 // float4 index, coalesced
        float4 wv = *(const float4*)&wr[k4 * 4];
        float4 s0 = *(const float4*)&g_vis[(size_t)(b0 + 0) * HH + k4 * 4];
        float4 s1 = *(const float4*)&g_vis[(size_t)(b0 + 1) * HH + k4 * 4];
        float4 s2 = *(const float4*)&g_vis[(size_t)(b0 + 2) * HH + k4 * 4];
        float4 s3 = *(const float4*)&g_vis[(size_t)(b0 + 3) * HH + k4 * 4];
        a0 += s0.x * wv.x + s0.y * wv.y + s0.z * wv.z + s0.w * wv.w;
        a1 += s1.x * wv.x + s1.y * wv.y + s1.z * wv.z + s1.w * wv.w;
        a2 += s2.x * wv.x + s2.y * wv.y + s2.z * wv.z + s2.w * wv.w;
        a3 += s3.x * wv.x + s3.y * wv.y + s3.z * wv.z + s3.w * wv.w;
    }
    #pragma unroll
    for (int off = 16; off; off >>= 1) {
        a0 += __shfl_xor_sync(0xFFFFFFFFu, a0, off);
        a1 += __shfl_xor_sync(0xFFFFFFFFu, a1, off);
        a2 += __shfl_xor_sync(0xFFFFFFFFu, a2, off);
        a3 += __shfl_xor_sync(0xFFFFFFFFu, a3, off);
    }
    if (lane == 0) {
        float bb = bias[n];
        g_v2[(size_t)(b0 + 0) * HH + n] = a0 + bb;
        g_v2[(size_t)(b0 + 1) * HH + n] = a1 + bb;
        g_v2[(size_t)(b0 + 2) * HH + n] = a2 + bb;
        g_v2[(size_t)(b0 + 3) * HH + n] = a3 + bb;
    }
}

// ---------------------------------------------------------------------------
// Kernel: mma.sync bf16-split GEMM, single-wave grid.
// out[m][n] = sum_k agg[m][k]*W1[n][k] + g_v2[m/S][n]
// BM=160, BN=128, BK=32, 24 stages, 3 smem buffers, grid (6,20)=120 CTAs
// (<=148 SMs: NO second wave). 8 warps 2(m)x4(n); warp tile 80x32.
// D = Ah.Bh + Ah.Bl + Al.Bh (fp32 acc).
// ---------------------------------------------------------------------------
#define BM 160
#define NSTG 24
#define NBUF 3
#define ROWH 40                       // padded row length in halfs (80 B)
#define STGA (BM * ROWH)              // A halfs per stage (6400)
#define STGB (128 * ROWH)             // B halfs per stage (5120)
#define GEMM_SMEM ((2 * NBUF * STGA + 2 * NBUF * STGB) * 2)   // 138240 B

__global__ __launch_bounds__(256) void gemm_kernel(float* __restrict__ out) {
    extern __shared__ unsigned short sm[];
    unsigned short* sAh = sm;
    unsigned short* sAl = sAh + NBUF * STGA;
    unsigned short* sBh = sAl + NBUF * STGA;
    unsigned short* sBl = sBh + NBUF * STGB;

    const int tid = threadIdx.x;
    const int lane = tid & 31;
    const int wid = tid >> 5;
    const int wm = wid >> 2;          // 0..1 -> m offset wm*80
    const int wn = wid & 3;           // 0..3 -> n offset wn*32
    const int n0 = blockIdx.x * 128;
    const int m0 = blockIdx.y * BM;

    const uint32_t bAh = smem_u32(sAh), bAl = smem_u32(sAl);
    const uint32_t bBh = smem_u32(sBh), bBl = smem_u32(sBl);

    float acc[5][4][4];
    #pragma unroll
    for (int i = 0; i < 5; i++)
        #pragma unroll
        for (int j = 0; j < 4; j++)
            #pragma unroll
            for (int r = 0; r < 4; r++) acc[i][j][r] = 0.f;

    auto issue_stage = [&](int s, int buf) {
        const int k0 = s * 32;
        // A: 160 rows x 4 chunks = 640 chunks of 16B
        #pragma unroll
        for (int j = 0; j < 3; j++) {
            int idx = tid + j * 256;
            if (idx < BM * 4) {
                int row = idx >> 2;
                int c16 = idx & 3;
                int kk = k0 + c16 * 8;
                uint32_t soff = (uint32_t)(buf * STGA + row * ROWH + c16 * 8) * 2u;
                size_t ga = (size_t)(m0 + row) * HH + kk;
                cpasync16(bAh + soff, &g_ahi[ga]);
                cpasync16(bAl + soff, &g_alo[ga]);
            }
        }
        // B: 128 rows x 4 chunks = 512 chunks
        #pragma unroll
        for (int j = 0; j < 2; j++) {
            int idx = tid + j * 256;
            int row = idx >> 2;
            int c16 = idx & 3;
            int kk = k0 + c16 * 8;
            uint32_t soff = (uint32_t)(buf * STGB + row * ROWH + c16 * 8) * 2u;
            size_t gb = (size_t)(n0 + row) * HH + kk;
            cpasync16(bBh + soff, &g_w1h[gb]);
            cpasync16(bBl + soff, &g_w1l[gb]);
        }
        CP_COMMIT();
    };

    issue_stage(0, 0);
    issue_stage(1, 1);

    for (int s = 0; s < NSTG; s++) {
        if (s == NSTG - 1) asm volatile("cp.async.wait_group 0;" ::: "memory");
        else               asm volatile("cp.async.wait_group 1;" ::: "memory");
        __syncthreads();

        if (s + 2 < NSTG) issue_stage(s + 2, (s + 2) % NBUF);

        const int buf = s % NBUF;
        const uint32_t stgA = (uint32_t)(buf * STGA) * 2u;
        const uint32_t stgB = (uint32_t)(buf * STGB) * 2u;

        #pragma unroll
        for (int ks = 0; ks < 2; ks++) {
            const int kh = ks * 16;
            uint32_t a_h[5][4], a_l[5][4], b_h[4][2], b_l[4][2];

            #pragma unroll
            for (int ti = 0; ti < 5; ti++) {
                int mr = wm * 80 + ti * 16 + (lane & 15);
                uint32_t off = stgA + (uint32_t)(mr * ROWH + kh + (lane >> 4) * 8) * 2u;
                ldsm_x4(a_h[ti], bAh + off);
                ldsm_x4(a_l[ti], bAl + off);
            }
            #pragma unroll
            for (int tj = 0; tj < 4; tj++) {
                int nr = wn * 32 + tj * 8 + (lane & 7);
                uint32_t off = stgB + (uint32_t)(nr * ROWH + kh + ((lane >> 3) & 1) * 8) * 2u;
                ldsm_x2(b_h[tj], bBh + off);
                ldsm_x2(b_l[tj], bBl + off);
            }

            #pragma unroll
            for (int ti = 0; ti < 5; ti++)
                #pragma unroll
                for (int tj = 0; tj < 4; tj++) {
                    mma_bf16(acc[ti][tj], a_h[ti], b_h[tj]);
                    mma_bf16(acc[ti][tj], a_h[ti], b_l[tj]);
                    mma_bf16(acc[ti][tj], a_l[ti], b_h[tj]);
                }
        }
    }
    __syncthreads();   // all warps done before smem reuse

    // Epilogue: fragments -> padded fp32 smem tile -> coalesced store + v2 add.
    float* st = (float*)sm;                     // 160 x 129 floats = 82560 B
    const int g = lane >> 2;
    const int t2 = (lane & 3) * 2;
    #pragma unroll
    for (int ti = 0; ti < 5; ti++)
        #pragma unroll
        for (int tj = 0; tj < 4; tj++) {
            int r0 = wm * 80 + ti * 16 + g;
            int c0 = wn * 32 + tj * 8 + t2;
            st[r0 * 129 + c0]           = acc[ti][tj][0];
            st[r0 * 129 + c0 + 1]       = acc[ti][tj][1];
            st[(r0 + 8) * 129 + c0]     = acc[ti][tj][2];
            st[(r0 + 8) * 129 + c0 + 1] = acc[ti][tj][3];
        }
    __syncthreads();

    #pragma unroll 4
    for (int it = 0; it < BM * 128 / 256; it++) {
        int q = tid + it * 256;
        int row = q >> 7;
        int col = q & 127;
        int m = m0 + row;
        int b = m / SS;
        out[(size_t)m * HH + n0 + col] = st[row * 129 + col] + g_v2[(size_t)b * HH + n0 + col];
    }
}

// ---------------------------------------------------------------------------
extern "C" void kernel_launch(void* const* d_in, const int* in_sizes, int n_in,
                              void* d_out, int out_size) {
    const float* feat = (const float*)d_in[0];   // (B, NV+T, H) f32
    const int*   mask = (const int*)d_in[1];     // (B, T) i32
    const float* w    = (const float*)d_in[2];   // (H, 2H) f32
    const float* bias = (const float*)d_in[3];   // (H,) f32
    float* out = (float*)d_out;                  // (B, S, H) f32

    // Single stream: stream/event creation during capture trips the
    // allocation guard (R7), so producers run sequentially.
    vis_part_kernel<<<dim3(BB, 4), 192>>>(feat);
    vis_fin_kernel<<<BB, 192>>>();
    v2_kernel<<<dim3(96, 8), 256>>>(w, bias);
    wconv_kernel<<<HH * HH / 4 / 512, 256>>>(w);
    agg_kernel<<<BSROWS, 192>>>(feat, mask);

    cudaFuncSetAttribute(gemm_kernel, cudaFuncAttributeMaxDynamicSharedMemorySize, GEMM_SMEM);
    gemm_kernel<<<dim3(HH / 128, BSROWS / BM), 256, GEMM_SMEM>>>(out);
}

// round 9
// speedup vs baseline: 2.6065x; 1.0314x over previous
#include <cuda_runtime.h>
#include <cuda_bf16.h>
#include <stdint.h>

// Problem constants
#define BB 32
#define TT 2000
#define HH 768
#define SS 100
#define NVV 100
#define BSROWS 3200            // B*S
#define ROWSTRIDE 2100         // NV + T
#define K2 1536                // 2*H

// Block-range layout of mega_kernel
#define NBLK_AGG  BSROWS                 // 3200
#define NBLK_VIS  (BB * 4)               // 128
#define NBLK_WC   384                    // 384 * 384 f4 = 147456 = H*H/4
#define NBLK_MEGA (NBLK_AGG + NBLK_VIS + NBLK_WC)   // 3712

// ---------------------------------------------------------------------------
// Scratch (device globals; allocation forbidden)
// ---------------------------------------------------------------------------
__device__ unsigned short g_ahi[BSROWS * HH];   // bf16 hi of segment means
__device__ unsigned short g_alo[BSROWS * HH];   // bf16 lo
__device__ unsigned short g_w1h[HH * HH];       // bf16 hi of W1 (w[:, :768])
__device__ unsigned short g_w1l[HH * HH];
__device__ float g_vispart[BB * 4 * HH];        // partial sums of vision rows
__device__ float g_v2[BB * HH];                 // vision @ W2^T + bias

// ---------------------------------------------------------------------------
// Helpers
// ---------------------------------------------------------------------------
__device__ __forceinline__ uint32_t smem_u32(const void* p) {
    uint32_t a;
    asm("{ .reg .u64 t; cvta.to.shared.u64 t, %1; cvt.u32.u64 %0, t; }" : "=r"(a) : "l"(p));
    return a;
}
__device__ __forceinline__ void cpasync16(uint32_t saddr, const void* g) {
    asm volatile("cp.async.cg.shared.global [%0], [%1], 16;" :: "r"(saddr), "l"(g));
}
#define CP_COMMIT() asm volatile("cp.async.commit_group;" ::: "memory")

__device__ __forceinline__ void ldsm_x4(uint32_t* r, uint32_t addr) {
    asm volatile("ldmatrix.sync.aligned.m8n8.x4.shared.b16 {%0,%1,%2,%3}, [%4];"
                 : "=r"(r[0]), "=r"(r[1]), "=r"(r[2]), "=r"(r[3]) : "r"(addr));
}
__device__ __forceinline__ void ldsm_x2(uint32_t* r, uint32_t addr) {
    asm volatile("ldmatrix.sync.aligned.m8n8.x2.shared.b16 {%0,%1}, [%2];"
                 : "=r"(r[0]), "=r"(r[1]) : "r"(addr));
}
__device__ __forceinline__ void mma_bf16(float* c, const uint32_t* a, const uint32_t* b) {
    asm volatile("mma.sync.aligned.m16n8k16.row.col.f32.bf16.bf16.f32 "
                 "{%0,%1,%2,%3}, {%4,%5,%6,%7}, {%8,%9}, {%0,%1,%2,%3};"
                 : "+f"(c[0]), "+f"(c[1]), "+f"(c[2]), "+f"(c[3])
                 : "r"(a[0]), "r"(a[1]), "r"(a[2]), "r"(a[3]), "r"(b[0]), "r"(b[1]));
}

// bf16 hi/lo split
__device__ __forceinline__ void split1(float x, unsigned short& h, unsigned short& l) {
    __nv_bfloat16 bh = __float2bfloat16_rn(x);
    h = __bfloat16_as_ushort(bh);
    l = __bfloat16_as_ushort(__float2bfloat16_rn(x - __bfloat162float(bh)));
}

// ---------------------------------------------------------------------------
// Mega kernel: block-range specialization fuses the three independent
// producers (agg / vision partials / W1 split) so they overlap on-chip.
// 192 threads per block.
// ---------------------------------------------------------------------------
__global__ __launch_bounds__(192) void mega_kernel(const float* __restrict__ feat,
                                                   const int* __restrict__ mask,
                                                   const float* __restrict__ w) {
    const int blk = blockIdx.x;

    if (blk < NBLK_AGG) {
        // ---- segment means -> bf16 hi/lo. One block per (b, s). ----
        int b = blk / SS;
        int s = blk % SS;

        __shared__ int s_list[TT];
        __shared__ int s_cnt;
        if (threadIdx.x == 0) s_cnt = 0;
        __syncthreads();

        const int* mrow = mask + (size_t)b * TT;
        for (int t = threadIdx.x; t < TT; t += 192) {
            if (mrow[t] == s + 1) {
                int pos = atomicAdd(&s_cnt, 1);
                s_list[pos] = t;
            }
        }
        __syncthreads();

        int cnt = s_cnt;
        float inv = (cnt > 0) ? (1.0f / (float)cnt) : 0.0f;

        const float* base = feat + ((size_t)b * ROWSTRIDE + NVV) * HH;
        int h4 = threadIdx.x;                       // 0..191
        float4 acc = make_float4(0.f, 0.f, 0.f, 0.f);
        int i = 0;
        for (; i + 8 <= cnt; i += 8) {              // 8 independent loads
            float4 v[8];
            #pragma unroll
            for (int j = 0; j < 8; j++)
                v[j] = *(const float4*)&base[(size_t)s_list[i + j] * HH + h4 * 4];
            #pragma unroll
            for (int j = 0; j < 8; j++) {
                acc.x += v[j].x; acc.y += v[j].y; acc.z += v[j].z; acc.w += v[j].w;
            }
        }
        for (; i + 4 <= cnt; i += 4) {
            float4 v[4];
            #pragma unroll
            for (int j = 0; j < 4; j++)
                v[j] = *(const float4*)&base[(size_t)s_list[i + j] * HH + h4 * 4];
            #pragma unroll
            for (int j = 0; j < 4; j++) {
                acc.x += v[j].x; acc.y += v[j].y; acc.z += v[j].z; acc.w += v[j].w;
            }
        }
        for (; i < cnt; i++) {
            float4 v = *(const float4*)&base[(size_t)s_list[i] * HH + h4 * 4];
            acc.x += v.x; acc.y += v.y; acc.z += v.z; acc.w += v.w;
        }
        acc.x *= inv; acc.y *= inv; acc.z *= inv; acc.w *= inv;

        ushort4 hh, ll;
        split1(acc.x, hh.x, ll.x); split1(acc.y, hh.y, ll.y);
        split1(acc.z, hh.z, ll.z); split1(acc.w, hh.w, ll.w);
        size_t o = (size_t)blk * HH + h4 * 4;
        *(ushort4*)&g_ahi[o] = hh;
        *(ushort4*)&g_alo[o] = ll;

    } else if (blk < NBLK_AGG + NBLK_VIS) {
        // ---- vision partial sums: 25 rows per block ----
        int idx = blk - NBLK_AGG;
        int b = idx >> 2, part = idx & 3;
        const float* base = feat + ((size_t)b * ROWSTRIDE + part * 25) * HH;
        int h4 = threadIdx.x;
        float4 acc = make_float4(0.f, 0.f, 0.f, 0.f);
        int r = 0;
        for (; r + 4 <= 25; r += 4) {
            float4 v0 = *(const float4*)&base[(size_t)(r + 0) * HH + h4 * 4];
            float4 v1 = *(const float4*)&base[(size_t)(r + 1) * HH + h4 * 4];
            float4 v2 = *(const float4*)&base[(size_t)(r + 2) * HH + h4 * 4];
            float4 v3 = *(const float4*)&base[(size_t)(r + 3) * HH + h4 * 4];
            acc.x += v0.x + v1.x + v2.x + v3.x;
            acc.y += v0.y + v1.y + v2.y + v3.y;
            acc.z += v0.z + v1.z + v2.z + v3.z;
            acc.w += v0.w + v1.w + v2.w + v3.w;
        }
        for (; r < 25; r++) {
            float4 v = *(const float4*)&base[(size_t)r * HH + h4 * 4];
            acc.x += v.x; acc.y += v.y; acc.z += v.z; acc.w += v.w;
        }
        *(float4*)&g_vispart[(size_t)idx * HH + h4 * 4] = acc;

    } else {
        // ---- W1 split: 384 float4s per block (2 per thread) ----
        int wblk = blk - (NBLK_AGG + NBLK_VIS);
        int i0 = wblk * 384 + threadIdx.x;
        #pragma unroll
        for (int j = 0; j < 2; j++) {
            int idx = i0 + j * 192;
            int n = idx / (HH / 4);
            int k4 = idx % (HH / 4);
            float4 v = *(const float4*)&w[(size_t)n * K2 + k4 * 4];
            ushort4 hh, ll;
            split1(v.x, hh.x, ll.x); split1(v.y, hh.y, ll.y);
            split1(v.z, hh.z, ll.z); split1(v.w, hh.w, ll.w);
            size_t o = (size_t)n * HH + k4 * 4;
            *(ushort4*)&g_w1h[o] = hh;
            *(ushort4*)&g_w1l[o] = ll;
        }
    }
}

// ---------------------------------------------------------------------------
// Kernel: g_v2[b][n] = vision_mean[b] . W2[n] + bias[n].
// Warp-per-n, 4 batches per warp; vision mean computed inline from partials.
// grid (96, 8), 256 threads.
// ---------------------------------------------------------------------------
__global__ __launch_bounds__(256) void v2_kernel(const float* __restrict__ w,
                                                 const float* __restrict__ bias) {
    const int lane = threadIdx.x & 31;
    const int wid = threadIdx.x >> 5;
    const int n = blockIdx.x * 8 + wid;         // 0..767
    const int b0 = blockIdx.y * 4;              // 0,4,...,28
    const float invN = 1.0f / (float)NVV;

    const float* wr = w + (size_t)n * K2 + HH;  // W2 row n
    float a0 = 0.f, a1 = 0.f, a2 = 0.f, a3 = 0.f;
    #pragma unroll
    for (int i = 0; i < 6; i++) {
        int k4 = i * 32 + lane;                 // float4 index, coalesced
        float4 wv = *(const float4*)&wr[k4 * 4];
        #pragma unroll
        for (int bb = 0; bb < 4; bb++) {
            const float* pp = &g_vispart[(size_t)((b0 + bb) * 4) * HH + k4 * 4];
            float4 p0 = *(const float4*)(pp);
            float4 p1 = *(const float4*)(pp + HH);
            float4 p2 = *(const float4*)(pp + 2 * HH);
            float4 p3 = *(const float4*)(pp + 3 * HH);
            float sx = (p0.x + p1.x + p2.x + p3.x) * invN;
            float sy = (p0.y + p1.y + p2.y + p3.y) * invN;
            float sz = (p0.z + p1.z + p2.z + p3.z) * invN;
            float sw = (p0.w + p1.w + p2.w + p3.w) * invN;
            float d = sx * wv.x + sy * wv.y + sz * wv.z + sw * wv.w;
            if (bb == 0) a0 += d;
            else if (bb == 1) a1 += d;
            else if (bb == 2) a2 += d;
            else a3 += d;
        }
    }
    #pragma unroll
    for (int off = 16; off; off >>= 1) {
        a0 += __shfl_xor_sync(0xFFFFFFFFu, a0, off);
        a1 += __shfl_xor_sync(0xFFFFFFFFu, a1, off);
        a2 += __shfl_xor_sync(0xFFFFFFFFu, a2, off);
        a3 += __shfl_xor_sync(0xFFFFFFFFu, a3, off);
    }
    if (lane == 0) {
        float bb = bias[n];
        g_v2[(size_t)(b0 + 0) * HH + n] = a0 + bb;
        g_v2[(size_t)(b0 + 1) * HH + n] = a1 + bb;
        g_v2[(size_t)(b0 + 2) * HH + n] = a2 + bb;
        g_v2[(size_t)(b0 + 3) * HH + n] = a3 + bb;
    }
}

// ---------------------------------------------------------------------------
// Kernel: mma.sync bf16-split GEMM, single-wave grid.
// out[m][n] = sum_k agg[m][k]*W1[n][k] + g_v2[m/S][n]
// BM=160, BN=128, BK=32, 24 stages, 3 smem buffers, grid (6,20)=120 CTAs.
// 8 warps 2(m)x4(n); warp tile 80x32. D = Ah.Bh + Ah.Bl + Al.Bh (fp32 acc).
// ---------------------------------------------------------------------------
#define BM 160
#define NSTG 24
#define NBUF 3
#define ROWH 40                       // padded row length in halfs (80 B)
#define STGA (BM * ROWH)              // A halfs per stage (6400)
#define STGB (128 * ROWH)             // B halfs per stage (5120)
#define GEMM_SMEM ((2 * NBUF * STGA + 2 * NBUF * STGB) * 2)   // 138240 B

__global__ __launch_bounds__(256) void gemm_kernel(float* __restrict__ out) {
    extern __shared__ unsigned short sm[];
    unsigned short* sAh = sm;
    unsigned short* sAl = sAh + NBUF * STGA;
    unsigned short* sBh = sAl + NBUF * STGA;
    unsigned short* sBl = sBh + NBUF * STGB;

    const int tid = threadIdx.x;
    const int lane = tid & 31;
    const int wid = tid >> 5;
    const int wm = wid >> 2;          // 0..1 -> m offset wm*80
    const int wn = wid & 3;           // 0..3 -> n offset wn*32
    const int n0 = blockIdx.x * 128;
    const int m0 = blockIdx.y * BM;

    const uint32_t bAh = smem_u32(sAh), bAl = smem_u32(sAl);
    const uint32_t bBh = smem_u32(sBh), bBl = smem_u32(sBl);

    float acc[5][4][4];
    #pragma unroll
    for (int i = 0; i < 5; i++)
        #pragma unroll
        for (int j = 0; j < 4; j++)
            #pragma unroll
            for (int r = 0; r < 4; r++) acc[i][j][r] = 0.f;

    auto issue_stage = [&](int s, int buf) {
        const int k0 = s * 32;
        #pragma unroll
        for (int j = 0; j < 3; j++) {
            int idx = tid + j * 256;
            if (idx < BM * 4) {
                int row = idx >> 2;
                int c16 = idx & 3;
                int kk = k0 + c16 * 8;
                uint32_t soff = (uint32_t)(buf * STGA + row * ROWH + c16 * 8) * 2u;
                size_t ga = (size_t)(m0 + row) * HH + kk;
                cpasync16(bAh + soff, &g_ahi[ga]);
                cpasync16(bAl + soff, &g_alo[ga]);
            }
        }
        #pragma unroll
        for (int j = 0; j < 2; j++) {
            int idx = tid + j * 256;
            int row = idx >> 2;
            int c16 = idx & 3;
            int kk = k0 + c16 * 8;
            uint32_t soff = (uint32_t)(buf * STGB + row * ROWH + c16 * 8) * 2u;
            size_t gb = (size_t)(n0 + row) * HH + kk;
            cpasync16(bBh + soff, &g_w1h[gb]);
            cpasync16(bBl + soff, &g_w1l[gb]);
        }
        CP_COMMIT();
    };

    issue_stage(0, 0);
    issue_stage(1, 1);

    for (int s = 0; s < NSTG; s++) {
        if (s == NSTG - 1) asm volatile("cp.async.wait_group 0;" ::: "memory");
        else               asm volatile("cp.async.wait_group 1;" ::: "memory");
        __syncthreads();

        if (s + 2 < NSTG) issue_stage(s + 2, (s + 2) % NBUF);

        const int buf = s % NBUF;
        const uint32_t stgA = (uint32_t)(buf * STGA) * 2u;
        const uint32_t stgB = (uint32_t)(buf * STGB) * 2u;

        #pragma unroll
        for (int ks = 0; ks < 2; ks++) {
            const int kh = ks * 16;
            uint32_t a_h[5][4], a_l[5][4], b_h[4][2], b_l[4][2];

            #pragma unroll
            for (int ti = 0; ti < 5; ti++) {
                int mr = wm * 80 + ti * 16 + (lane & 15);
                uint32_t off = stgA + (uint32_t)(mr * ROWH + kh + (lane >> 4) * 8) * 2u;
                ldsm_x4(a_h[ti], bAh + off);
                ldsm_x4(a_l[ti], bAl + off);
            }
            #pragma unroll
            for (int tj = 0; tj < 4; tj++) {
                int nr = wn * 32 + tj * 8 + (lane & 7);
                uint32_t off = stgB + (uint32_t)(nr * ROWH + kh + ((lane >> 3) & 1) * 8) * 2u;
                ldsm_x2(b_h[tj], bBh + off);
                ldsm_x2(b_l[tj], bBl + off);
            }

            #pragma unroll
            for (int ti = 0; ti < 5; ti++)
                #pragma unroll
                for (int tj = 0; tj < 4; tj++) {
                    mma_bf16(acc[ti][tj], a_h[ti], b_h[tj]);
                    mma_bf16(acc[ti][tj], a_h[ti], b_l[tj]);
                    mma_bf16(acc[ti][tj], a_l[ti], b_h[tj]);
                }
        }
    }
    __syncthreads();   // all warps done before smem reuse

    // Epilogue: fragments -> padded fp32 smem tile -> coalesced store + v2 add.
    float* st = (float*)sm;                     // 160 x 129 floats = 82560 B
    const int g = lane >> 2;
    const int t2 = (lane & 3) * 2;
    #pragma unroll
    for (int ti = 0; ti < 5; ti++)
        #pragma unroll
        for (int tj = 0; tj < 4; tj++) {
            int r0 = wm * 80 + ti * 16 + g;
            int c0 = wn * 32 + tj * 8 + t2;
            st[r0 * 129 + c0]           = acc[ti][tj][0];
            st[r0 * 129 + c0 + 1]       = acc[ti][tj][1];
            st[(r0 + 8) * 129 + c0]     = acc[ti][tj][2];
            st[(r0 + 8) * 129 + c0 + 1] = acc[ti][tj][3];
        }
    __syncthreads();

    #pragma unroll 4
    for (int it = 0; it < BM * 128 / 256; it++) {
        int q = tid + it * 256;
        int row = q >> 7;
        int col = q & 127;
        int m = m0 + row;
        int b = m / SS;
        out[(size_t)m * HH + n0 + col] = st[row * 129 + col] + g_v2[(size_t)b * HH + n0 + col];
    }
}

// ---------------------------------------------------------------------------
extern "C" void kernel_launch(void* const* d_in, const int* in_sizes, int n_in,
                              void* d_out, int out_size) {
    const float* feat = (const float*)d_in[0];   // (B, NV+T, H) f32
    const int*   mask = (const int*)d_in[1];     // (B, T) i32
    const float* w    = (const float*)d_in[2];   // (H, 2H) f32
    const float* bias = (const float*)d_in[3];   // (H,) f32
    float* out = (float*)d_out;                  // (B, S, H) f32

    mega_kernel<<<NBLK_MEGA, 192>>>(feat, mask, w);
    v2_kernel<<<dim3(96, 8), 256>>>(w, bias);

    cudaFuncSetAttribute(gemm_kernel, cudaFuncAttributeMaxDynamicSharedMemorySize, GEMM_SMEM);
    gemm_kernel<<<dim3(HH / 128, BSROWS / BM), 256, GEMM_SMEM>>>(out);
}

// round 10
// speedup vs baseline: 2.9506x; 1.1320x over previous
#include <cuda_runtime.h>
#include <cuda_fp16.h>
#include <stdint.h>

// Problem constants
#define BB 32
#define TT 2000
#define HH 768
#define SS 100
#define NVV 100
#define BSROWS 3200            // B*S
#define ROWSTRIDE 2100         // NV + T
#define K2 1536                // 2*H

// Block-range layout of mega_kernel
#define NBLK_AGG  BSROWS                 // 3200
#define NBLK_VIS  (BB * 4)               // 128
#define NBLK_WC   384                    // 384 * 384 f4 = H*H/4
#define NBLK_MEGA (NBLK_AGG + NBLK_VIS + NBLK_WC)   // 3712

// ---------------------------------------------------------------------------
// Scratch (device globals; allocation forbidden)
// ---------------------------------------------------------------------------
__device__ unsigned short g_af[BSROWS * HH];    // fp16 segment means (A)
__device__ unsigned short g_w1h[HH * HH];       // fp16 hi of W1 (w[:, :768])
__device__ unsigned short g_w1l[HH * HH];       // fp16 lo of W1
__device__ float g_vispart[BB * 4 * HH];        // partial sums of vision rows
__device__ float g_v2[BB * HH];                 // vision @ W2^T + bias

// ---------------------------------------------------------------------------
// Helpers
// ---------------------------------------------------------------------------
__device__ __forceinline__ uint32_t smem_u32(const void* p) {
    uint32_t a;
    asm("{ .reg .u64 t; cvta.to.shared.u64 t, %1; cvt.u32.u64 %0, t; }" : "=r"(a) : "l"(p));
    return a;
}
__device__ __forceinline__ void cpasync16(uint32_t saddr, const void* g) {
    asm volatile("cp.async.cg.shared.global [%0], [%1], 16;" :: "r"(saddr), "l"(g));
}
#define CP_COMMIT() asm volatile("cp.async.commit_group;" ::: "memory")

__device__ __forceinline__ void ldsm_x4(uint32_t* r, uint32_t addr) {
    asm volatile("ldmatrix.sync.aligned.m8n8.x4.shared.b16 {%0,%1,%2,%3}, [%4];"
                 : "=r"(r[0]), "=r"(r[1]), "=r"(r[2]), "=r"(r[3]) : "r"(addr));
}
__device__ __forceinline__ void ldsm_x2(uint32_t* r, uint32_t addr) {
    asm volatile("ldmatrix.sync.aligned.m8n8.x2.shared.b16 {%0,%1}, [%2];"
                 : "=r"(r[0]), "=r"(r[1]) : "r"(addr));
}
__device__ __forceinline__ void mma_f16(float* c, const uint32_t* a, const uint32_t* b) {
    asm volatile("mma.sync.aligned.m16n8k16.row.col.f32.f16.f16.f32 "
                 "{%0,%1,%2,%3}, {%4,%5,%6,%7}, {%8,%9}, {%0,%1,%2,%3};"
                 : "+f"(c[0]), "+f"(c[1]), "+f"(c[2]), "+f"(c[3])
                 : "r"(a[0]), "r"(a[1]), "r"(a[2]), "r"(a[3]), "r"(b[0]), "r"(b[1]));
}

// fp16 hi/lo split (for W1)
__device__ __forceinline__ void splitw(float x, unsigned short& h, unsigned short& l) {
    __half hh = __float2half_rn(x);
    h = __half_as_ushort(hh);
    l = __half_as_ushort(__float2half_rn(x - __half2float(hh)));
}
// pack 4 floats -> 4 fp16 in a uint2
__device__ __forceinline__ uint2 pack4h(float4 v) {
    __half2 p01 = __floats2half2_rn(v.x, v.y);
    __half2 p23 = __floats2half2_rn(v.z, v.w);
    uint2 u;
    u.x = *reinterpret_cast<uint32_t*>(&p01);
    u.y = *reinterpret_cast<uint32_t*>(&p23);
    return u;
}

// ---------------------------------------------------------------------------
// Mega kernel: block-range specialization fuses agg / vision partials / W1
// split so they overlap on-chip. 192 threads per block.
// ---------------------------------------------------------------------------
__global__ __launch_bounds__(192) void mega_kernel(const float* __restrict__ feat,
                                                   const int* __restrict__ mask,
                                                   const float* __restrict__ w) {
    const int blk = blockIdx.x;

    if (blk < NBLK_AGG) {
        // ---- segment means -> fp16. One block per (b, s). ----
        int b = blk / SS;
        int s = blk % SS;

        __shared__ int s_list[TT];
        __shared__ int s_cnt;
        if (threadIdx.x == 0) s_cnt = 0;
        __syncthreads();

        const int* mrow = mask + (size_t)b * TT;
        for (int t = threadIdx.x; t < TT; t += 192) {
            if (mrow[t] == s + 1) {
                int pos = atomicAdd(&s_cnt, 1);
                s_list[pos] = t;
            }
        }
        __syncthreads();

        int cnt = s_cnt;
        float inv = (cnt > 0) ? (1.0f / (float)cnt) : 0.0f;

        const float* base = feat + ((size_t)b * ROWSTRIDE + NVV) * HH;
        int h4 = threadIdx.x;                       // 0..191
        float4 acc = make_float4(0.f, 0.f, 0.f, 0.f);
        int i = 0;
        for (; i + 8 <= cnt; i += 8) {              // 8 independent loads
            float4 v[8];
            #pragma unroll
            for (int j = 0; j < 8; j++)
                v[j] = *(const float4*)&base[(size_t)s_list[i + j] * HH + h4 * 4];
            #pragma unroll
            for (int j = 0; j < 8; j++) {
                acc.x += v[j].x; acc.y += v[j].y; acc.z += v[j].z; acc.w += v[j].w;
            }
        }
        for (; i + 4 <= cnt; i += 4) {
            float4 v[4];
            #pragma unroll
            for (int j = 0; j < 4; j++)
                v[j] = *(const float4*)&base[(size_t)s_list[i + j] * HH + h4 * 4];
            #pragma unroll
            for (int j = 0; j < 4; j++) {
                acc.x += v[j].x; acc.y += v[j].y; acc.z += v[j].z; acc.w += v[j].w;
            }
        }
        for (; i < cnt; i++) {
            float4 v = *(const float4*)&base[(size_t)s_list[i] * HH + h4 * 4];
            acc.x += v.x; acc.y += v.y; acc.z += v.z; acc.w += v.w;
        }
        acc.x *= inv; acc.y *= inv; acc.z *= inv; acc.w *= inv;

        *(uint2*)&g_af[(size_t)blk * HH + h4 * 4] = pack4h(acc);

    } else if (blk < NBLK_AGG + NBLK_VIS) {
        // ---- vision partial sums: 25 rows per block ----
        int idx = blk - NBLK_AGG;
        int b = idx >> 2, part = idx & 3;
        const float* base = feat + ((size_t)b * ROWSTRIDE + part * 25) * HH;
        int h4 = threadIdx.x;
        float4 acc = make_float4(0.f, 0.f, 0.f, 0.f);
        int r = 0;
        for (; r + 4 <= 25; r += 4) {
            float4 v0 = *(const float4*)&base[(size_t)(r + 0) * HH + h4 * 4];
            float4 v1 = *(const float4*)&base[(size_t)(r + 1) * HH + h4 * 4];
            float4 v2 = *(const float4*)&base[(size_t)(r + 2) * HH + h4 * 4];
            float4 v3 = *(const float4*)&base[(size_t)(r + 3) * HH + h4 * 4];
            acc.x += v0.x + v1.x + v2.x + v3.x;
            acc.y += v0.y + v1.y + v2.y + v3.y;
            acc.z += v0.z + v1.z + v2.z + v3.z;
            acc.w += v0.w + v1.w + v2.w + v3.w;
        }
        for (; r < 25; r++) {
            float4 v = *(const float4*)&base[(size_t)r * HH + h4 * 4];
            acc.x += v.x; acc.y += v.y; acc.z += v.z; acc.w += v.w;
        }
        *(float4*)&g_vispart[(size_t)idx * HH + h4 * 4] = acc;

    } else {
        // ---- W1 split into fp16 hi/lo: 384 float4s per block ----
        int wblk = blk - (NBLK_AGG + NBLK_VIS);
        int i0 = wblk * 384 + threadIdx.x;
        #pragma unroll
        for (int j = 0; j < 2; j++) {
            int idx = i0 + j * 192;
            int n = idx / (HH / 4);
            int k4 = idx % (HH / 4);
            float4 v = *(const float4*)&w[(size_t)n * K2 + k4 * 4];
            ushort4 hh, ll;
            splitw(v.x, hh.x, ll.x); splitw(v.y, hh.y, ll.y);
            splitw(v.z, hh.z, ll.z); splitw(v.w, hh.w, ll.w);
            size_t o = (size_t)n * HH + k4 * 4;
            *(ushort4*)&g_w1h[o] = hh;
            *(ushort4*)&g_w1l[o] = ll;
        }
    }
}

// ---------------------------------------------------------------------------
// Kernel: g_v2[b][n] = vision_mean[b] . W2[n] + bias[n].
// Warp-per-n, 4 batches per warp; vision mean computed inline from partials.
// grid (96, 8), 256 threads. Full fp32 (exact).
// ---------------------------------------------------------------------------
__global__ __launch_bounds__(256) void v2_kernel(const float* __restrict__ w,
                                                 const float* __restrict__ bias) {
    const int lane = threadIdx.x & 31;
    const int wid = threadIdx.x >> 5;
    const int n = blockIdx.x * 8 + wid;         // 0..767
    const int b0 = blockIdx.y * 4;              // 0,4,...,28
    const float invN = 1.0f / (float)NVV;

    const float* wr = w + (size_t)n * K2 + HH;  // W2 row n
    float a0 = 0.f, a1 = 0.f, a2 = 0.f, a3 = 0.f;
    #pragma unroll
    for (int i = 0; i < 6; i++) {
        int k4 = i * 32 + lane;                 // float4 index, coalesced
        float4 wv = *(const float4*)&wr[k4 * 4];
        #pragma unroll
        for (int bb = 0; bb < 4; bb++) {
            const float* pp = &g_vispart[(size_t)((b0 + bb) * 4) * HH + k4 * 4];
            float4 p0 = *(const float4*)(pp);
            float4 p1 = *(const float4*)(pp + HH);
            float4 p2 = *(const float4*)(pp + 2 * HH);
            float4 p3 = *(const float4*)(pp + 3 * HH);
            float sx = (p0.x + p1.x + p2.x + p3.x) * invN;
            float sy = (p0.y + p1.y + p2.y + p3.y) * invN;
            float sz = (p0.z + p1.z + p2.z + p3.z) * invN;
            float sw = (p0.w + p1.w + p2.w + p3.w) * invN;
            float d = sx * wv.x + sy * wv.y + sz * wv.z + sw * wv.w;
            if (bb == 0) a0 += d;
            else if (bb == 1) a1 += d;
            else if (bb == 2) a2 += d;
            else a3 += d;
        }
    }
    #pragma unroll
    for (int off = 16; off; off >>= 1) {
        a0 += __shfl_xor_sync(0xFFFFFFFFu, a0, off);
        a1 += __shfl_xor_sync(0xFFFFFFFFu, a1, off);
        a2 += __shfl_xor_sync(0xFFFFFFFFu, a2, off);
        a3 += __shfl_xor_sync(0xFFFFFFFFu, a3, off);
    }
    if (lane == 0) {
        float bb = bias[n];
        g_v2[(size_t)(b0 + 0) * HH + n] = a0 + bb;
        g_v2[(size_t)(b0 + 1) * HH + n] = a1 + bb;
        g_v2[(size_t)(b0 + 2) * HH + n] = a2 + bb;
        g_v2[(size_t)(b0 + 3) * HH + n] = a3 + bb;
    }
}

// ---------------------------------------------------------------------------
// Kernel: mma.sync fp16 2-term GEMM, single-wave grid.
// out[m][n] = sum_k A[m][k]*(W1h+W1l)[n][k] + g_v2[m/S][n]
// A single fp16; W1 split fp16 hi/lo (only error source: A rounding ~1e-4).
// BM=160, BN=128, BK=32, 24 stages, 3 smem buffers, grid (6,20)=120 CTAs.
// 8 warps 2(m)x4(n); warp tile 80x32.
// ---------------------------------------------------------------------------
#define BM 160
#define NSTG 24
#define NBUF 3
#define ROWH 40                       // padded row length in halfs (80 B)
#define STGA (BM * ROWH)              // A halfs per stage (6400)
#define STGB (128 * ROWH)             // B halfs per stage (5120)
#define GEMM_SMEM ((NBUF * STGA + 2 * NBUF * STGB) * 2)   // 99840 B

__global__ __launch_bounds__(256) void gemm_kernel(float* __restrict__ out) {
    extern __shared__ unsigned short sm[];
    unsigned short* sA  = sm;
    unsigned short* sBh = sA + NBUF * STGA;
    unsigned short* sBl = sBh + NBUF * STGB;

    const int tid = threadIdx.x;
    const int lane = tid & 31;
    const int wid = tid >> 5;
    const int wm = wid >> 2;          // 0..1 -> m offset wm*80
    const int wn = wid & 3;           // 0..3 -> n offset wn*32
    const int n0 = blockIdx.x * 128;
    const int m0 = blockIdx.y * BM;

    const uint32_t bA = smem_u32(sA), bBh = smem_u32(sBh), bBl = smem_u32(sBl);

    float acc[5][4][4];
    #pragma unroll
    for (int i = 0; i < 5; i++)
        #pragma unroll
        for (int j = 0; j < 4; j++)
            #pragma unroll
            for (int r = 0; r < 4; r++) acc[i][j][r] = 0.f;

    auto issue_stage = [&](int s, int buf) {
        const int k0 = s * 32;
        // A: 160 rows x 4 chunks = 640 chunks of 16B
        #pragma unroll
        for (int j = 0; j < 3; j++) {
            int idx = tid + j * 256;
            if (idx < BM * 4) {
                int row = idx >> 2;
                int c16 = idx & 3;
                int kk = k0 + c16 * 8;
                uint32_t soff = (uint32_t)(buf * STGA + row * ROWH + c16 * 8) * 2u;
                cpasync16(bA + soff, &g_af[(size_t)(m0 + row) * HH + kk]);
            }
        }
        // B: 128 rows x 4 chunks, hi + lo
        #pragma unroll
        for (int j = 0; j < 2; j++) {
            int idx = tid + j * 256;
            int row = idx >> 2;
            int c16 = idx & 3;
            int kk = k0 + c16 * 8;
            uint32_t soff = (uint32_t)(buf * STGB + row * ROWH + c16 * 8) * 2u;
            size_t gb = (size_t)(n0 + row) * HH + kk;
            cpasync16(bBh + soff, &g_w1h[gb]);
            cpasync16(bBl + soff, &g_w1l[gb]);
        }
        CP_COMMIT();
    };

    issue_stage(0, 0);
    issue_stage(1, 1);

    for (int s = 0; s < NSTG; s++) {
        if (s == NSTG - 1) asm volatile("cp.async.wait_group 0;" ::: "memory");
        else               asm volatile("cp.async.wait_group 1;" ::: "memory");
        __syncthreads();

        if (s + 2 < NSTG) issue_stage(s + 2, (s + 2) % NBUF);

        const int buf = s % NBUF;
        const uint32_t stgA = (uint32_t)(buf * STGA) * 2u;
        const uint32_t stgB = (uint32_t)(buf * STGB) * 2u;

        #pragma unroll
        for (int ks = 0; ks < 2; ks++) {
            const int kh = ks * 16;
            uint32_t a[5][4], b_h[4][2], b_l[4][2];

            #pragma unroll
            for (int ti = 0; ti < 5; ti++) {
                int mr = wm * 80 + ti * 16 + (lane & 15);
                uint32_t off = stgA + (uint32_t)(mr * ROWH + kh + (lane >> 4) * 8) * 2u;
                ldsm_x4(a[ti], bA + off);
            }
            #pragma unroll
            for (int tj = 0; tj < 4; tj++) {
                int nr = wn * 32 + tj * 8 + (lane & 7);
                uint32_t off = stgB + (uint32_t)(nr * ROWH + kh + ((lane >> 3) & 1) * 8) * 2u;
                ldsm_x2(b_h[tj], bBh + off);
                ldsm_x2(b_l[tj], bBl + off);
            }

            #pragma unroll
            for (int ti = 0; ti < 5; ti++)
                #pragma unroll
                for (int tj = 0; tj < 4; tj++) {
                    mma_f16(acc[ti][tj], a[ti], b_h[tj]);
                    mma_f16(acc[ti][tj], a[ti], b_l[tj]);
                }
        }
    }
    __syncthreads();   // all warps done before smem reuse

    // Epilogue: fragments -> padded fp32 smem tile -> coalesced store + v2 add.
    float* st = (float*)sm;                     // 160 x 129 floats = 82560 B
    const int g = lane >> 2;
    const int t2 = (lane & 3) * 2;
    #pragma unroll
    for (int ti = 0; ti < 5; ti++)
        #pragma unroll
        for (int tj = 0; tj < 4; tj++) {
            int r0 = wm * 80 + ti * 16 + g;
            int c0 = wn * 32 + tj * 8 + t2;
            st[r0 * 129 + c0]           = acc[ti][tj][0];
            st[r0 * 129 + c0 + 1]       = acc[ti][tj][1];
            st[(r0 + 8) * 129 + c0]     = acc[ti][tj][2];
            st[(r0 + 8) * 129 + c0 + 1] = acc[ti][tj][3];
        }
    __syncthreads();

    #pragma unroll 4
    for (int it = 0; it < BM * 128 / 256; it++) {
        int q = tid + it * 256;
        int row = q >> 7;
        int col = q & 127;
        int m = m0 + row;
        int b = m / SS;
        out[(size_t)m * HH + n0 + col] = st[row * 129 + col] + g_v2[(size_t)b * HH + n0 + col];
    }
}

// ---------------------------------------------------------------------------
extern "C" void kernel_launch(void* const* d_in, const int* in_sizes, int n_in,
                              void* d_out, int out_size) {
    const float* feat = (const float*)d_in[0];   // (B, NV+T, H) f32
    const int*   mask = (const int*)d_in[1];     // (B, T) i32
    const float* w    = (const float*)d_in[2];   // (H, 2H) f32
    const float* bias = (const float*)d_in[3];   // (H,) f32
    float* out = (float*)d_out;                  // (B, S, H) f32

    mega_kernel<<<NBLK_MEGA, 192>>>(feat, mask, w);
    v2_kernel<<<dim3(96, 8), 256>>>(w, bias);

    cudaFuncSetAttribute(gemm_kernel, cudaFuncAttributeMaxDynamicSharedMemorySize, GEMM_SMEM);
    gemm_kernel<<<dim3(HH / 128, BSROWS / BM), 256, GEMM_SMEM>>>(out);
}

// round 11
// speedup vs baseline: 2.9574x; 1.0023x over previous
#include <cuda_runtime.h>
#include <cuda_fp16.h>
#include <stdint.h>

// Problem constants
#define BB 32
#define TT 2000
#define HH 768
#define SS 100
#define NVV 100
#define BSROWS 3200            // B*S
#define ROWSTRIDE 2100         // NV + T
#define K2 1536                // 2*H

// Block-range layout of mega_kernel (agg blocks handle TWO segments each)
#define NBLK_AGG  (BSROWS / 2)           // 1600
#define NBLK_VIS  (BB * 4)               // 128
#define NBLK_WC   384                    // 384 * 384 f4 = H*H/4
#define NBLK_MEGA (NBLK_AGG + NBLK_VIS + NBLK_WC)   // 2112

// ---------------------------------------------------------------------------
// Scratch (device globals; allocation forbidden)
// ---------------------------------------------------------------------------
__device__ unsigned short g_af[BSROWS * HH];    // fp16 segment means (A)
__device__ unsigned short g_w1h[HH * HH];       // fp16 hi of W1 (w[:, :768])
__device__ unsigned short g_w1l[HH * HH];       // fp16 lo of W1
__device__ float g_vispart[BB * 4 * HH];        // partial sums of vision rows
__device__ float g_v2[BB * HH];                 // vision @ W2^T + bias

// ---------------------------------------------------------------------------
// Helpers
// ---------------------------------------------------------------------------
__device__ __forceinline__ uint32_t smem_u32(const void* p) {
    uint32_t a;
    asm("{ .reg .u64 t; cvta.to.shared.u64 t, %1; cvt.u32.u64 %0, t; }" : "=r"(a) : "l"(p));
    return a;
}
__device__ __forceinline__ void cpasync16(uint32_t saddr, const void* g) {
    asm volatile("cp.async.cg.shared.global [%0], [%1], 16;" :: "r"(saddr), "l"(g));
}
#define CP_COMMIT() asm volatile("cp.async.commit_group;" ::: "memory")

__device__ __forceinline__ void ldsm_x4(uint32_t* r, uint32_t addr) {
    asm volatile("ldmatrix.sync.aligned.m8n8.x4.shared.b16 {%0,%1,%2,%3}, [%4];"
                 : "=r"(r[0]), "=r"(r[1]), "=r"(r[2]), "=r"(r[3]) : "r"(addr));
}
__device__ __forceinline__ void ldsm_x2(uint32_t* r, uint32_t addr) {
    asm volatile("ldmatrix.sync.aligned.m8n8.x2.shared.b16 {%0,%1}, [%2];"
                 : "=r"(r[0]), "=r"(r[1]) : "r"(addr));
}
__device__ __forceinline__ void mma_f16(float* c, const uint32_t* a, const uint32_t* b) {
    asm volatile("mma.sync.aligned.m16n8k16.row.col.f32.f16.f16.f32 "
                 "{%0,%1,%2,%3}, {%4,%5,%6,%7}, {%8,%9}, {%0,%1,%2,%3};"
                 : "+f"(c[0]), "+f"(c[1]), "+f"(c[2]), "+f"(c[3])
                 : "r"(a[0]), "r"(a[1]), "r"(a[2]), "r"(a[3]), "r"(b[0]), "r"(b[1]));
}

// fp16 hi/lo split (for W1)
__device__ __forceinline__ void splitw(float x, unsigned short& h, unsigned short& l) {
    __half hh = __float2half_rn(x);
    h = __half_as_ushort(hh);
    l = __half_as_ushort(__float2half_rn(x - __half2float(hh)));
}
// pack 4 floats -> 4 fp16 in a uint2
__device__ __forceinline__ uint2 pack4h(float4 v) {
    __half2 p01 = __floats2half2_rn(v.x, v.y);
    __half2 p23 = __floats2half2_rn(v.z, v.w);
    uint2 u;
    u.x = *reinterpret_cast<uint32_t*>(&p01);
    u.y = *reinterpret_cast<uint32_t*>(&p23);
    return u;
}

// accumulate a segment's rows (list in smem) into a float4 and store fp16 mean
__device__ __forceinline__ void seg_accum_store(const float* __restrict__ base,
                                                const int* __restrict__ list,
                                                int cnt, int h4, size_t orow) {
    float inv = (cnt > 0) ? (1.0f / (float)cnt) : 0.0f;
    float4 acc = make_float4(0.f, 0.f, 0.f, 0.f);
    int i = 0;
    for (; i + 8 <= cnt; i += 8) {
        float4 v[8];
        #pragma unroll
        for (int j = 0; j < 8; j++)
            v[j] = *(const float4*)&base[(size_t)list[i + j] * HH + h4 * 4];
        #pragma unroll
        for (int j = 0; j < 8; j++) {
            acc.x += v[j].x; acc.y += v[j].y; acc.z += v[j].z; acc.w += v[j].w;
        }
    }
    for (; i + 4 <= cnt; i += 4) {
        float4 v[4];
        #pragma unroll
        for (int j = 0; j < 4; j++)
            v[j] = *(const float4*)&base[(size_t)list[i + j] * HH + h4 * 4];
        #pragma unroll
        for (int j = 0; j < 4; j++) {
            acc.x += v[j].x; acc.y += v[j].y; acc.z += v[j].z; acc.w += v[j].w;
        }
    }
    for (; i < cnt; i++) {
        float4 v = *(const float4*)&base[(size_t)list[i] * HH + h4 * 4];
        acc.x += v.x; acc.y += v.y; acc.z += v.z; acc.w += v.w;
    }
    acc.x *= inv; acc.y *= inv; acc.z *= inv; acc.w *= inv;
    *(uint2*)&g_af[orow * HH + h4 * 4] = pack4h(acc);
}

// ---------------------------------------------------------------------------
// Mega kernel: block-range specialization fuses agg (2 segments per block) /
// vision partials / W1 split so they overlap on-chip. 192 threads per block.
// ---------------------------------------------------------------------------
__global__ __launch_bounds__(192) void mega_kernel(const float* __restrict__ feat,
                                                   const int* __restrict__ mask,
                                                   const float* __restrict__ w) {
    const int blk = blockIdx.x;

    if (blk < NBLK_AGG) {
        // ---- segment means -> fp16. One block per (b, segment-pair). ----
        int b = blk / (SS / 2);
        int s0 = (blk % (SS / 2)) * 2;          // segments s0, s0+1

        __shared__ int list0[TT], list1[TT];
        __shared__ int cnt0, cnt1;
        if (threadIdx.x == 0) { cnt0 = 0; cnt1 = 0; }
        __syncthreads();

        const int* mrow = mask + (size_t)b * TT;
        for (int t = threadIdx.x; t < TT; t += 192) {
            int m = mrow[t];
            if (m == s0 + 1)      list0[atomicAdd(&cnt0, 1)] = t;
            else if (m == s0 + 2) list1[atomicAdd(&cnt1, 1)] = t;
        }
        __syncthreads();

        const float* base = feat + ((size_t)b * ROWSTRIDE + NVV) * HH;
        int h4 = threadIdx.x;                       // 0..191
        size_t row0 = (size_t)b * SS + s0;
        seg_accum_store(base, list0, cnt0, h4, row0);
        seg_accum_store(base, list1, cnt1, h4, row0 + 1);

    } else if (blk < NBLK_AGG + NBLK_VIS) {
        // ---- vision partial sums: 25 rows per block ----
        int idx = blk - NBLK_AGG;
        int b = idx >> 2, part = idx & 3;
        const float* base = feat + ((size_t)b * ROWSTRIDE + part * 25) * HH;
        int h4 = threadIdx.x;
        float4 acc = make_float4(0.f, 0.f, 0.f, 0.f);
        int r = 0;
        for (; r + 4 <= 25; r += 4) {
            float4 v0 = *(const float4*)&base[(size_t)(r + 0) * HH + h4 * 4];
            float4 v1 = *(const float4*)&base[(size_t)(r + 1) * HH + h4 * 4];
            float4 v2 = *(const float4*)&base[(size_t)(r + 2) * HH + h4 * 4];
            float4 v3 = *(const float4*)&base[(size_t)(r + 3) * HH + h4 * 4];
            acc.x += v0.x + v1.x + v2.x + v3.x;
            acc.y += v0.y + v1.y + v2.y + v3.y;
            acc.z += v0.z + v1.z + v2.z + v3.z;
            acc.w += v0.w + v1.w + v2.w + v3.w;
        }
        for (; r < 25; r++) {
            float4 v = *(const float4*)&base[(size_t)r * HH + h4 * 4];
            acc.x += v.x; acc.y += v.y; acc.z += v.z; acc.w += v.w;
        }
        *(float4*)&g_vispart[(size_t)idx * HH + h4 * 4] = acc;

    } else {
        // ---- W1 split into fp16 hi/lo: 384 float4s per block ----
        int wblk = blk - (NBLK_AGG + NBLK_VIS);
        int i0 = wblk * 384 + threadIdx.x;
        #pragma unroll
        for (int j = 0; j < 2; j++) {
            int idx = i0 + j * 192;
            int n = idx / (HH / 4);
            int k4 = idx % (HH / 4);
            float4 v = *(const float4*)&w[(size_t)n * K2 + k4 * 4];
            ushort4 hh, ll;
            splitw(v.x, hh.x, ll.x); splitw(v.y, hh.y, ll.y);
            splitw(v.z, hh.z, ll.z); splitw(v.w, hh.w, ll.w);
            size_t o = (size_t)n * HH + k4 * 4;
            *(ushort4*)&g_w1h[o] = hh;
            *(ushort4*)&g_w1l[o] = ll;
        }
    }
}

// ---------------------------------------------------------------------------
// Kernel: g_v2[b][n] = vision_mean[b] . W2[n] + bias[n].
// Warp-per-n, 4 batches per warp; vision mean computed inline from partials.
// grid (96, 8), 256 threads. Full fp32 (exact).
// ---------------------------------------------------------------------------
__global__ __launch_bounds__(256) void v2_kernel(const float* __restrict__ w,
                                                 const float* __restrict__ bias) {
    const int lane = threadIdx.x & 31;
    const int wid = threadIdx.x >> 5;
    const int n = blockIdx.x * 8 + wid;         // 0..767
    const int b0 = blockIdx.y * 4;              // 0,4,...,28
    const float invN = 1.0f / (float)NVV;

    const float* wr = w + (size_t)n * K2 + HH;  // W2 row n
    float a0 = 0.f, a1 = 0.f, a2 = 0.f, a3 = 0.f;
    #pragma unroll
    for (int i = 0; i < 6; i++) {
        int k4 = i * 32 + lane;                 // float4 index, coalesced
        float4 wv = *(const float4*)&wr[k4 * 4];
        #pragma unroll
        for (int bb = 0; bb < 4; bb++) {
            const float* pp = &g_vispart[(size_t)((b0 + bb) * 4) * HH + k4 * 4];
            float4 p0 = *(const float4*)(pp);
            float4 p1 = *(const float4*)(pp + HH);
            float4 p2 = *(const float4*)(pp + 2 * HH);
            float4 p3 = *(const float4*)(pp + 3 * HH);
            float sx = (p0.x + p1.x + p2.x + p3.x) * invN;
            float sy = (p0.y + p1.y + p2.y + p3.y) * invN;
            float sz = (p0.z + p1.z + p2.z + p3.z) * invN;
            float sw = (p0.w + p1.w + p2.w + p3.w) * invN;
            float d = sx * wv.x + sy * wv.y + sz * wv.z + sw * wv.w;
            if (bb == 0) a0 += d;
            else if (bb == 1) a1 += d;
            else if (bb == 2) a2 += d;
            else a3 += d;
        }
    }
    #pragma unroll
    for (int off = 16; off; off >>= 1) {
        a0 += __shfl_xor_sync(0xFFFFFFFFu, a0, off);
        a1 += __shfl_xor_sync(0xFFFFFFFFu, a1, off);
        a2 += __shfl_xor_sync(0xFFFFFFFFu, a2, off);
        a3 += __shfl_xor_sync(0xFFFFFFFFu, a3, off);
    }
    if (lane == 0) {
        float bb = bias[n];
        g_v2[(size_t)(b0 + 0) * HH + n] = a0 + bb;
        g_v2[(size_t)(b0 + 1) * HH + n] = a1 + bb;
        g_v2[(size_t)(b0 + 2) * HH + n] = a2 + bb;
        g_v2[(size_t)(b0 + 3) * HH + n] = a3 + bb;
    }
}

// ---------------------------------------------------------------------------
// Kernel: mma.sync fp16 2-term GEMM, single-wave grid, 4-deep pipeline.
// out[m][n] = sum_k A[m][k]*(W1h+W1l)[n][k] + g_v2[m/S][n]
// BM=160, BN=128, BK=32, 24 stages, 4 smem buffers (prefetch dist ~2.5),
// grid (6,20)=120 CTAs. 8 warps 2(m)x4(n); warp tile 80x32.
// ---------------------------------------------------------------------------
#define BM 160
#define NSTG 24
#define NBUF 4
#define ROWH 40                       // padded row length in halfs (80 B)
#define STGA (BM * ROWH)              // A halfs per stage (6400)
#define STGB (128 * ROWH)             // B halfs per stage (5120)
#define GEMM_SMEM ((NBUF * STGA + 2 * NBUF * STGB) * 2)   // 133120 B

__global__ __launch_bounds__(256) void gemm_kernel(float* __restrict__ out) {
    extern __shared__ unsigned short sm[];
    unsigned short* sA  = sm;
    unsigned short* sBh = sA + NBUF * STGA;
    unsigned short* sBl = sBh + NBUF * STGB;

    const int tid = threadIdx.x;
    const int lane = tid & 31;
    const int wid = tid >> 5;
    const int wm = wid >> 2;          // 0..1 -> m offset wm*80
    const int wn = wid & 3;           // 0..3 -> n offset wn*32
    const int n0 = blockIdx.x * 128;
    const int m0 = blockIdx.y * BM;

    const uint32_t bA = smem_u32(sA), bBh = smem_u32(sBh), bBl = smem_u32(sBl);

    float acc[5][4][4];
    #pragma unroll
    for (int i = 0; i < 5; i++)
        #pragma unroll
        for (int j = 0; j < 4; j++)
            #pragma unroll
            for (int r = 0; r < 4; r++) acc[i][j][r] = 0.f;

    auto issue_stage = [&](int s, int buf) {
        const int k0 = s * 32;
        #pragma unroll
        for (int j = 0; j < 3; j++) {
            int idx = tid + j * 256;
            if (idx < BM * 4) {
                int row = idx >> 2;
                int c16 = idx & 3;
                int kk = k0 + c16 * 8;
                uint32_t soff = (uint32_t)(buf * STGA + row * ROWH + c16 * 8) * 2u;
                cpasync16(bA + soff, &g_af[(size_t)(m0 + row) * HH + kk]);
            }
        }
        #pragma unroll
        for (int j = 0; j < 2; j++) {
            int idx = tid + j * 256;
            int row = idx >> 2;
            int c16 = idx & 3;
            int kk = k0 + c16 * 8;
            uint32_t soff = (uint32_t)(buf * STGB + row * ROWH + c16 * 8) * 2u;
            size_t gb = (size_t)(n0 + row) * HH + kk;
            cpasync16(bBh + soff, &g_w1h[gb]);
            cpasync16(bBl + soff, &g_w1l[gb]);
        }
        CP_COMMIT();
    };

    issue_stage(0, 0);
    issue_stage(1, 1);
    issue_stage(2, 2);

    for (int s = 0; s < NSTG; s++) {
        // ensure stage s's group is complete (tail-clamped depth)
        int rem = NSTG - 1 - s;
        if (rem >= 3)      asm volatile("cp.async.wait_group 2;" ::: "memory");
        else if (rem == 2) asm volatile("cp.async.wait_group 2;" ::: "memory");
        else if (rem == 1) asm volatile("cp.async.wait_group 1;" ::: "memory");
        else               asm volatile("cp.async.wait_group 0;" ::: "memory");
        __syncthreads();

        if (s + 3 < NSTG) issue_stage(s + 3, (s + 3) % NBUF);

        const int buf = s % NBUF;
        const uint32_t stgA = (uint32_t)(buf * STGA) * 2u;
        const uint32_t stgB = (uint32_t)(buf * STGB) * 2u;

        #pragma unroll
        for (int ks = 0; ks < 2; ks++) {
            const int kh = ks * 16;
            uint32_t a[5][4], b_h[4][2], b_l[4][2];

            #pragma unroll
            for (int ti = 0; ti < 5; ti++) {
                int mr = wm * 80 + ti * 16 + (lane & 15);
                uint32_t off = stgA + (uint32_t)(mr * ROWH + kh + (lane >> 4) * 8) * 2u;
                ldsm_x4(a[ti], bA + off);
            }
            #pragma unroll
            for (int tj = 0; tj < 4; tj++) {
                int nr = wn * 32 + tj * 8 + (lane & 7);
                uint32_t off = stgB + (uint32_t)(nr * ROWH + kh + ((lane >> 3) & 1) * 8) * 2u;
                ldsm_x2(b_h[tj], bBh + off);
                ldsm_x2(b_l[tj], bBl + off);
            }

            #pragma unroll
            for (int ti = 0; ti < 5; ti++)
                #pragma unroll
                for (int tj = 0; tj < 4; tj++) {
                    mma_f16(acc[ti][tj], a[ti], b_h[tj]);
                    mma_f16(acc[ti][tj], a[ti], b_l[tj]);
                }
        }
    }
    __syncthreads();   // all warps done before smem reuse

    // Epilogue: fragments -> padded fp32 smem tile -> coalesced store + v2 add.
    float* st = (float*)sm;                     // 160 x 129 floats = 82560 B
    const int g = lane >> 2;
    const int t2 = (lane & 3) * 2;
    #pragma unroll
    for (int ti = 0; ti < 5; ti++)
        #pragma unroll
        for (int tj = 0; tj < 4; tj++) {
            int r0 = wm * 80 + ti * 16 + g;
            int c0 = wn * 32 + tj * 8 + t2;
            st[r0 * 129 + c0]           = acc[ti][tj][0];
            st[r0 * 129 + c0 + 1]       = acc[ti][tj][1];
            st[(r0 + 8) * 129 + c0]     = acc[ti][tj][2];
            st[(r0 + 8) * 129 + c0 + 1] = acc[ti][tj][3];
        }
    __syncthreads();

    #pragma unroll 4
    for (int it = 0; it < BM * 128 / 256; it++) {
        int q = tid + it * 256;
        int row = q >> 7;
        int col = q & 127;
        int m = m0 + row;
        int b = m / SS;
        out[(size_t)m * HH + n0 + col] = st[row * 129 + col] + g_v2[(size_t)b * HH + n0 + col];
    }
}

// ---------------------------------------------------------------------------
extern "C" void kernel_launch(void* const* d_in, const int* in_sizes, int n_in,
                              void* d_out, int out_size) {
    const float* feat = (const float*)d_in[0];   // (B, NV+T, H) f32
    const int*   mask = (const int*)d_in[1];     // (B, T) i32
    const float* w    = (const float*)d_in[2];   // (H, 2H) f32
    const float* bias = (const float*)d_in[3];   // (H,) f32
    float* out = (float*)d_out;                  // (B, S, H) f32

    mega_kernel<<<NBLK_MEGA, 192>>>(feat, mask, w);
    v2_kernel<<<dim3(96, 8), 256>>>(w, bias);

    cudaFuncSetAttribute(gemm_kernel, cudaFuncAttributeMaxDynamicSharedMemorySize, GEMM_SMEM);
    gemm_kernel<<<dim3(HH / 128, BSROWS / BM), 256, GEMM_SMEM>>>(out);
}